// round 13
// baseline (speedup 1.0000x reference)
#include <cuda_runtime.h>
#include <math.h>
#include <stdint.h>

// ---------------------------------------------------------------------------
// Problem constants
// ---------------------------------------------------------------------------
#define Bn  2
#define Sn  1024
#define Dn  1024
#define Mn  8
#define Rn  128
#define NNEUR 256
#define NH  16
#define DH  64
#define BS  (Bn * Sn)          // 2048 tokens
#define MR  (Mn * Rn)          // 1024
#define NF  2816               // merged feat width: 768 gate + 1024 qk + 1024 v

// GEMM smem geometry (3-stage cp.async pipeline), templated on BN
#define A_STRIDE 20            // floats per A row (16 data + 4 pad)
#define A_STG (128 * A_STRIDE) // 2560 floats per stage
#define SMEM_B256 (3 * (A_STG + 16 * (256 + 8)) * 4)   // 81408 bytes
#define SMEM_B128 (3 * (A_STG + 16 * (128 + 8)) * 4)   // 56832 bytes

// ---------------------------------------------------------------------------
// Device scratch (allocation-free: __device__ globals)
// ---------------------------------------------------------------------------
__device__ float d_x32[BS * Dn];               // tf32-rounded x
__device__ float d_Bfeat[Dn * NF];             // [Wg_q|Wg_k|Wg_v|qk_f|v_f] tf32
__device__ float d_CF[BS * NF];                // logits(768) + allh_qk + allh_v
__device__ float d_Br[2 * MR * Dn];            // tf32 qk_r ; v_r
__device__ float d_Wo32[Dn * Dn];              // tf32 W_O
__device__ float d_g[3 * BS * Mn];             // grouped gates (q,k,v)
__device__ float d_hq[BS * Rn];
__device__ float d_hk[BS * Rn];
__device__ float d_hv[BS * Rn];
__device__ float d_aeff3[3 * BS * MR];         // (g⊗h) tf32
__device__ float d_QKV[3 * BS * Dn];           // Q ; K ; V (tf32)
__device__ float d_attn[BS * Dn];              // attention out (tf32)

// ---------------------------------------------------------------------------
// TF32 helpers
// ---------------------------------------------------------------------------
__device__ __forceinline__ float to_tf32(float x) {
    uint32_t u;
    asm("cvt.rna.tf32.f32 %0, %1;" : "=r"(u) : "f"(x));
    return __uint_as_float(u);
}

__device__ __forceinline__ void mma_tf32(float c[4], const uint32_t a[4],
                                         uint32_t b0, uint32_t b1) {
    asm volatile(
        "mma.sync.aligned.m16n8k8.row.col.f32.tf32.tf32.f32 "
        "{%0,%1,%2,%3}, {%4,%5,%6,%7}, {%8,%9}, {%0,%1,%2,%3};\n"
        : "+f"(c[0]), "+f"(c[1]), "+f"(c[2]), "+f"(c[3])
        : "r"(a[0]), "r"(a[1]), "r"(a[2]), "r"(a[3]), "r"(b0), "r"(b1));
}

#define CPA(dst, src) \
    asm volatile("cp.async.cg.shared.global [%0], [%1], 16;\n" :: "r"(dst), "l"(src))
#define CPCOMMIT() asm volatile("cp.async.commit_group;\n")
#define CPWAIT2()  asm volatile("cp.async.wait_group 2;\n")

// ---------------------------------------------------------------------------
// TF32 GEMM body, K = 1024 fixed (64 k-tiles of 16). Templated tile width.
// BM=128, BN in {128,256}; 256 threads, 8 warps; warp tile 64 x (BN/4).
// 3-stage cp.async pipeline. Inputs must already be tf32-rounded.
// ---------------------------------------------------------------------------
template <int BN>
__device__ __forceinline__ void
gemm_ca_body(const float* __restrict__ A, const float* __restrict__ B,
             float* __restrict__ C, int lda, int ldb, int ldc, bool cvtOut)
{
    constexpr int BSTR = BN + 8;            // padded B row (floats)
    constexpr int BSTG = 16 * BSTR;         // B stage floats
    constexpr int NJ   = BN / 32;           // n8 tiles per warp (4 or 8)

    extern __shared__ float sm[];
    float* As = sm;                          // 3 stages [128][A_STRIDE]
    float* Bs = sm + 3 * A_STG;              // 3 stages [16][BSTR]

    const int tid  = threadIdx.x;
    const int brow = blockIdx.y * 128;
    const int bcol = blockIdx.x * BN;

    const int warp = tid >> 5;
    const int lane = tid & 31;
    const int wm   = warp >> 2;              // 0..1
    const int wn   = warp & 3;               // 0..3
    const int grp  = lane >> 2;
    const int tg   = lane & 3;
    const int m0   = wm * 64;
    const int n0w  = wn * (BN / 4);

    // A cp.async mapping: 128x16 floats, 2 x 16B per thread
    const int aRow = tid >> 2;               // 0..63
    const int aCol = (tid & 3) << 2;         // 0,4,8,12
    const float* Asrc0 = A + (size_t)(brow + aRow) * lda + aCol;
    const float* Asrc1 = Asrc0 + (size_t)64 * lda;

    // B cp.async mapping: 16xBN floats, BN/64 x 16B per thread
    const int bRow  = tid >> 4;              // 0..15
    const int bCol0 = (tid & 15) << 2;       // 0..60
    const float* Bsrc = B + (size_t)bRow * ldb + bcol + bCol0;

    const uint32_t aBase = (uint32_t)__cvta_generic_to_shared(As);
    const uint32_t bBase = (uint32_t)__cvta_generic_to_shared(Bs);
    const uint32_t sA0 = aBase + (uint32_t)(aRow * A_STRIDE + aCol) * 4;
    const uint32_t sA1 = sA0 + 64 * A_STRIDE * 4;
    const uint32_t sB0 = bBase + (uint32_t)(bRow * BSTR + bCol0) * 4;

#define ISSUE(s_, t_) do {                                                     \
        const uint32_t oa = (uint32_t)(s_) * (A_STG * 4);                      \
        const uint32_t ob = (uint32_t)(s_) * (BSTG * 4);                       \
        CPA(sA0 + oa, Asrc0 + ((t_) << 4));                                    \
        CPA(sA1 + oa, Asrc1 + ((t_) << 4));                                    \
        _Pragma("unroll")                                                      \
        for (int c_ = 0; c_ < BN / 64; c_++)                                   \
            CPA(sB0 + ob + c_ * 256, Bsrc + (size_t)((t_) << 4) * ldb + c_ * 64); \
        CPCOMMIT(); } while (0)

    float c[4][NJ][4];
#pragma unroll
    for (int i = 0; i < 4; i++)
#pragma unroll
        for (int j = 0; j < NJ; j++)
#pragma unroll
            for (int r = 0; r < 4; r++) c[i][j][r] = 0.f;

    ISSUE(0, 0);
    ISSUE(1, 1);
    ISSUE(2, 2);

    for (int t = 0; t < 64; t++) {
        const int s = t % 3;
        CPWAIT2();
        __syncthreads();

        const float* Ast = As + s * A_STG;
        const float* Bst = Bs + s * BSTG;

#pragma unroll
        for (int ks = 0; ks < 2; ks++) {
            const int kb = ks << 3;
            uint32_t af[4][4], bf[NJ][2];
#pragma unroll
            for (int i = 0; i < 4; i++) {
                const int r0 = (m0 + i * 16 + grp) * A_STRIDE;
                af[i][0] = __float_as_uint(Ast[r0 + kb + tg]);
                af[i][1] = __float_as_uint(Ast[r0 + 8 * A_STRIDE + kb + tg]);
                af[i][2] = __float_as_uint(Ast[r0 + kb + tg + 4]);
                af[i][3] = __float_as_uint(Ast[r0 + 8 * A_STRIDE + kb + tg + 4]);
            }
#pragma unroll
            for (int j = 0; j < NJ; j++) {
                const int n0 = n0w + j * 8 + grp;
                bf[j][0] = __float_as_uint(Bst[(kb + tg) * BSTR + n0]);
                bf[j][1] = __float_as_uint(Bst[(kb + tg + 4) * BSTR + n0]);
            }
#pragma unroll
            for (int i = 0; i < 4; i++)
#pragma unroll
                for (int j = 0; j < NJ; j++)
                    mma_tf32(c[i][j], af[i], bf[j][0], bf[j][1]);
        }

        __syncthreads();
        if (t + 3 < 64) ISSUE(s, t + 3); else CPCOMMIT();
    }
#undef ISSUE

#pragma unroll
    for (int i = 0; i < 4; i++) {
        const int r0 = brow + m0 + i * 16 + grp;
#pragma unroll
        for (int j = 0; j < NJ; j++) {
            const int cc = bcol + n0w + j * 8 + tg * 2;
            float v0 = c[i][j][0], v1 = c[i][j][1], v2 = c[i][j][2], v3 = c[i][j][3];
            if (cvtOut) {
                v0 = to_tf32(v0); v1 = to_tf32(v1);
                v2 = to_tf32(v2); v3 = to_tf32(v3);
            }
            *(float2*)&C[(size_t)r0 * ldc + cc]       = make_float2(v0, v1);
            *(float2*)&C[(size_t)(r0 + 8) * ldc + cc] = make_float2(v2, v3);
        }
    }
}

// -------- GEMM wrappers ----------------------------------------------------
__global__ void __launch_bounds__(256, 1)
gemm_w256(const float* __restrict__ A, const float* __restrict__ B,
          float* __restrict__ C, int lda, int ldb, int ldc, int cvtOut)
{
    gemm_ca_body<256>(A, B, C, lda, ldb, ldc, cvtOut != 0);
}

__global__ void __launch_bounds__(256, 2)
gemm_w128(const float* __restrict__ A, const float* __restrict__ B,
          float* __restrict__ C, int lda, int ldb, int ldc, int cvtOut)
{
    gemm_ca_body<128>(A, B, C, lda, ldb, ldc, cvtOut != 0);
}

// restore: z 0..2 -> Q (qk_r), K (qk_r), V (v_r); outputs tf32-rounded
__global__ void __launch_bounds__(256, 1)
gemm_restore256()
{
    const int z = blockIdx.z;
    const float* A = d_aeff3 + (size_t)z * BS * MR;
    const float* B = d_Br + (z < 2 ? 0 : (size_t)MR * Dn);
    float* C = d_QKV + (size_t)z * BS * Dn;
    gemm_ca_body<256>(A, B, C, MR, Dn, Dn, true);
}

// ---------------------------------------------------------------------------
// pack_misc: tf32-round x, qk_r, v_r, W_O (float4 per thread)
// ---------------------------------------------------------------------------
#define X_ELEMS  (BS * Dn)          // 2097152
#define R_ELEMS  (MR * Dn)          // 1048576
__global__ void pack_misc(const float* __restrict__ x, const float* __restrict__ qk_r,
                          const float* __restrict__ v_r, const float* __restrict__ wo)
{
    const size_t i4 = ((size_t)blockIdx.x * 256 + threadIdx.x) * 4;
    const float* src;
    float* dst;
    size_t off;
    if (i4 < X_ELEMS)                     { src = x;    dst = d_x32;            off = i4; }
    else if (i4 < X_ELEMS + R_ELEMS)      { src = qk_r; dst = d_Br;             off = i4 - X_ELEMS; }
    else if (i4 < X_ELEMS + 2 * R_ELEMS)  { src = v_r;  dst = d_Br + R_ELEMS;   off = i4 - X_ELEMS - R_ELEMS; }
    else                                  { src = wo;   dst = d_Wo32;           off = i4 - X_ELEMS - 2 * R_ELEMS; }
    float4 v = *(const float4*)(src + off);
    *(float4*)(dst + off) = make_float4(to_tf32(v.x), to_tf32(v.y),
                                        to_tf32(v.z), to_tf32(v.w));
}

// ---------------------------------------------------------------------------
// pack_bfeat: build [D][2816] = [Wg_q|Wg_k|Wg_v|qk_f(m-major cols)|v_f]
// ---------------------------------------------------------------------------
__global__ void pack_bfeat(const float* __restrict__ wq, const float* __restrict__ wk,
                           const float* __restrict__ wv, const float* __restrict__ qkf,
                           const float* __restrict__ vf)
{
    const int d = blockIdx.x;
    for (int col = threadIdx.x; col < NF; col += 256) {
        float v;
        if (col < 768) {
            const int which = col >> 8;
            const int n = col & 255;
            const float* w = (which == 0) ? wq : (which == 1) ? wk : wv;
            v = w[(size_t)d * NNEUR + n];
        } else if (col < 1792) {
            const int cc = col - 768;
            v = qkf[((size_t)(cc >> 7) * Dn + d) * Rn + (cc & 127)];
        } else {
            const int cc = col - 1792;
            v = vf[((size_t)(cc >> 7) * Dn + d) * Rn + (cc & 127)];
        }
        d_Bfeat[(size_t)d * NF + col] = to_tf32(v);
    }
}

// ---------------------------------------------------------------------------
// Gate softmax + grouping. Reads logits from d_CF (stride NF). grid=(BS,3).
// ---------------------------------------------------------------------------
__global__ void gate_kernel()
{
    const int token = blockIdx.x;
    const int which = blockIdx.y;
    const float* lp = d_CF + (size_t)token * NF + which * NNEUR;
    const int t = threadIdx.x;

    __shared__ float red[256];
    __shared__ float gs[8];

    float v = lp[t];
    red[t] = v; __syncthreads();
#pragma unroll
    for (int s = 128; s > 0; s >>= 1) {
        if (t < s) red[t] = fmaxf(red[t], red[t + s]);
        __syncthreads();
    }
    float mx = red[0];
    __syncthreads();

    float e = __expf(v - mx);
#pragma unroll
    for (int off = 16; off; off >>= 1)
        e += __shfl_down_sync(0xffffffffu, e, off);
    if ((t & 31) == 0) gs[t >> 5] = e;
    __syncthreads();

    if (t < 8) {
        float tot = 0.f;
#pragma unroll
        for (int i = 0; i < 8; i++) tot += gs[i];
        d_g[((size_t)which * BS + token) * Mn + t] = gs[t] / (tot * (1.0f + 1e-8f));
    }
}

// ---------------------------------------------------------------------------
// Mix: h[bs,r] = sum_m g[bs,m] * allh[bs,m,r]  (allh lives in d_CF cols 768+)
// ---------------------------------------------------------------------------
__global__ void mix_kernel()
{
    const int bs = blockIdx.x;
    const int r  = threadIdx.x;
    const float* gq = d_g + (size_t)bs * Mn;
    const float* gk = d_g + (size_t)BS * Mn + (size_t)bs * Mn;
    const float* gv = d_g + (size_t)2 * BS * Mn + (size_t)bs * Mn;
    const float* row = d_CF + (size_t)bs * NF;

    float hq = 0.f, hk = 0.f, hv = 0.f;
#pragma unroll
    for (int m = 0; m < Mn; m++) {
        float a  = row[768 + m * Rn + r];
        float av = row[1792 + m * Rn + r];
        hq = fmaf(gq[m], a, hq);
        hk = fmaf(gk[m], a, hk);
        hv = fmaf(gv[m], av, hv);
    }
    d_hq[bs * Rn + r] = hq;
    d_hk[bs * Rn + r] = hk;
    d_hv[bs * Rn + r] = hv;
}

// ---------------------------------------------------------------------------
// Aeff3[z][bs, m*R+r] = tf32(g_z[bs,m]*h_z[bs,r])
// ---------------------------------------------------------------------------
__global__ void aeff3_kernel()
{
    const int bs = blockIdx.x;
    const int cidx = threadIdx.x * 4;
    const int m = cidx >> 7;

    const float gq = d_g[(size_t)bs * Mn + m];
    const float gk = d_g[(size_t)BS * Mn + (size_t)bs * Mn + m];
    const float gv = d_g[(size_t)2 * BS * Mn + (size_t)bs * Mn + m];

    const int r = cidx & 127;
    float4 hq4 = *(const float4*)(d_hq + (size_t)bs * Rn + r);
    float4 hk4 = *(const float4*)(d_hk + (size_t)bs * Rn + r);
    float4 hv4 = *(const float4*)(d_hv + (size_t)bs * Rn + r);

    *(float4*)(d_aeff3 + (size_t)bs * MR + cidx) =
        make_float4(to_tf32(gq * hq4.x), to_tf32(gq * hq4.y),
                    to_tf32(gq * hq4.z), to_tf32(gq * hq4.w));
    *(float4*)(d_aeff3 + (size_t)BS * MR + (size_t)bs * MR + cidx) =
        make_float4(to_tf32(gk * hk4.x), to_tf32(gk * hk4.y),
                    to_tf32(gk * hk4.z), to_tf32(gk * hk4.w));
    *(float4*)(d_aeff3 + (size_t)2 * BS * MR + (size_t)bs * MR + cidx) =
        make_float4(to_tf32(gv * hv4.x), to_tf32(gv * hv4.y),
                    to_tf32(gv * hv4.z), to_tf32(gv * hv4.w));
}

// ---------------------------------------------------------------------------
// Tensor-core causal flash attention (TF32 m16n8k8). Q/K/V pre-rounded.
// Block 128 threads (4 warps), 64 query rows. Grid (S/64, B*NH).
// ---------------------------------------------------------------------------
__global__ void __launch_bounds__(128, 3)
flash_mma_kernel()
{
    __shared__ float Ks[64][68];
    __shared__ float Vs[64][72];

    const int tid  = threadIdx.x;
    const int warp = tid >> 5;
    const int lane = tid & 31;
    const int grp  = lane >> 2;
    const int tg   = lane & 3;
    const int qb   = blockIdx.x;
    const int bh   = blockIdx.y;
    const int b    = bh >> 4;
    const int h    = bh & 15;
    const int q0   = qb * 64;
    const int m0   = warp * 16;

    const float* Qg = d_QKV;
    const float* Kg = d_QKV + (size_t)BS * Dn;
    const float* Vg = d_QKV + (size_t)2 * BS * Dn;

    // stage Q tile (scale by 1/8 — exact power of two, stays tf32)
#pragma unroll
    for (int i = 0; i < 8; i++) {
        int idx = tid + i * 128;
        int row = idx >> 4, c = (idx & 15) * 4;
        float4 v = *(const float4*)(Qg + (size_t)(b * Sn + q0 + row) * Dn + h * DH + c);
        *(float4*)&Ks[row][c] = make_float4(v.x * 0.125f, v.y * 0.125f,
                                            v.z * 0.125f, v.w * 0.125f);
    }
    __syncthreads();

    uint32_t qf[8][4];
#pragma unroll
    for (int dk = 0; dk < 8; dk++) {
        qf[dk][0] = __float_as_uint(Ks[m0 + grp][dk * 8 + tg]);
        qf[dk][1] = __float_as_uint(Ks[m0 + grp + 8][dk * 8 + tg]);
        qf[dk][2] = __float_as_uint(Ks[m0 + grp][dk * 8 + tg + 4]);
        qf[dk][3] = __float_as_uint(Ks[m0 + grp + 8][dk * 8 + tg + 4]);
    }
    __syncthreads();

    float co[8][4];
#pragma unroll
    for (int j = 0; j < 8; j++)
#pragma unroll
        for (int r = 0; r < 4; r++) co[j][r] = 0.f;
    float mr0 = -1e30f, mr1 = -1e30f, l0 = 0.f, l1 = 0.f;

    for (int kt = 0; kt <= qb; kt++) {
        const int k0 = kt * 64;

#pragma unroll
        for (int i = 0; i < 8; i++) {
            int idx = tid + i * 128;
            int row = idx >> 4, c = (idx & 15) * 4;
            size_t g = (size_t)(b * Sn + k0 + row) * Dn + h * DH + c;
            *(float4*)&Ks[row][c] = *(const float4*)(Kg + g);
            *(float4*)&Vs[row][c] = *(const float4*)(Vg + g);
        }
        __syncthreads();

        float cs[8][4];
#pragma unroll
        for (int j = 0; j < 8; j++) {
#pragma unroll
            for (int r = 0; r < 4; r++) cs[j][r] = 0.f;
#pragma unroll
            for (int dk = 0; dk < 8; dk++) {
                uint32_t b0 = __float_as_uint(Ks[j * 8 + grp][dk * 8 + tg]);
                uint32_t b1 = __float_as_uint(Ks[j * 8 + grp][dk * 8 + tg + 4]);
                mma_tf32(cs[j], qf[dk], b0, b1);
            }
        }

        if (kt == qb) {
            const int r0 = q0 + m0 + grp;
            const int r1 = r0 + 8;
#pragma unroll
            for (int j = 0; j < 8; j++) {
                const int ca = k0 + j * 8 + 2 * tg;
                if (ca > r0)     cs[j][0] = -1e30f;
                if (ca + 1 > r0) cs[j][1] = -1e30f;
                if (ca > r1)     cs[j][2] = -1e30f;
                if (ca + 1 > r1) cs[j][3] = -1e30f;
            }
        }

        float mx0 = mr0, mx1 = mr1;
#pragma unroll
        for (int j = 0; j < 8; j++) {
            mx0 = fmaxf(mx0, fmaxf(cs[j][0], cs[j][1]));
            mx1 = fmaxf(mx1, fmaxf(cs[j][2], cs[j][3]));
        }
        mx0 = fmaxf(mx0, __shfl_xor_sync(0xffffffffu, mx0, 1));
        mx0 = fmaxf(mx0, __shfl_xor_sync(0xffffffffu, mx0, 2));
        mx1 = fmaxf(mx1, __shfl_xor_sync(0xffffffffu, mx1, 1));
        mx1 = fmaxf(mx1, __shfl_xor_sync(0xffffffffu, mx1, 2));

        float corr0 = __expf(mr0 - mx0);
        float corr1 = __expf(mr1 - mx1);
        mr0 = mx0; mr1 = mx1;

        float s0 = 0.f, s1 = 0.f;
#pragma unroll
        for (int j = 0; j < 8; j++) {
            cs[j][0] = __expf(cs[j][0] - mx0); s0 += cs[j][0];
            cs[j][1] = __expf(cs[j][1] - mx0); s0 += cs[j][1];
            cs[j][2] = __expf(cs[j][2] - mx1); s1 += cs[j][2];
            cs[j][3] = __expf(cs[j][3] - mx1); s1 += cs[j][3];
        }
        s0 += __shfl_xor_sync(0xffffffffu, s0, 1);
        s0 += __shfl_xor_sync(0xffffffffu, s0, 2);
        s1 += __shfl_xor_sync(0xffffffffu, s1, 1);
        s1 += __shfl_xor_sync(0xffffffffu, s1, 2);
        l0 = l0 * corr0 + s0;
        l1 = l1 * corr1 + s1;

#pragma unroll
        for (int j = 0; j < 8; j++) {
            co[j][0] *= corr0; co[j][1] *= corr0;
            co[j][2] *= corr1; co[j][3] *= corr1;
        }

        const int base = lane & ~3;
        const int s1l = base + (tg >> 1);
        const int s2l = s1l + 2;
        const bool odd = tg & 1;
#pragma unroll
        for (int kk = 0; kk < 8; kk++) {
            float v00 = __shfl_sync(0xffffffffu, cs[kk][0], s1l);
            float v01 = __shfl_sync(0xffffffffu, cs[kk][1], s1l);
            float v02 = __shfl_sync(0xffffffffu, cs[kk][0], s2l);
            float v03 = __shfl_sync(0xffffffffu, cs[kk][1], s2l);
            float v10 = __shfl_sync(0xffffffffu, cs[kk][2], s1l);
            float v11 = __shfl_sync(0xffffffffu, cs[kk][3], s1l);
            float v12 = __shfl_sync(0xffffffffu, cs[kk][2], s2l);
            float v13 = __shfl_sync(0xffffffffu, cs[kk][3], s2l);
            uint32_t ap[4];
            ap[0] = __float_as_uint(to_tf32(odd ? v01 : v00));
            ap[1] = __float_as_uint(to_tf32(odd ? v11 : v10));
            ap[2] = __float_as_uint(to_tf32(odd ? v03 : v02));
            ap[3] = __float_as_uint(to_tf32(odd ? v13 : v12));
#pragma unroll
            for (int j = 0; j < 8; j++) {
                uint32_t b0 = __float_as_uint(Vs[kk * 8 + tg][j * 8 + grp]);
                uint32_t b1 = __float_as_uint(Vs[kk * 8 + tg + 4][j * 8 + grp]);
                mma_tf32(co[j], ap, b0, b1);
            }
        }
        __syncthreads();
    }

    const float i0 = 1.f / l0;
    const float i1 = 1.f / l1;
    const int r0 = q0 + m0 + grp;
    float* op0 = d_attn + (size_t)(b * Sn + r0) * Dn + h * DH;
    float* op1 = d_attn + (size_t)(b * Sn + r0 + 8) * Dn + h * DH;
#pragma unroll
    for (int j = 0; j < 8; j++) {
        const int cc = j * 8 + 2 * tg;
        *(float2*)(op0 + cc) = make_float2(to_tf32(co[j][0] * i0), to_tf32(co[j][1] * i0));
        *(float2*)(op1 + cc) = make_float2(to_tf32(co[j][2] * i1), to_tf32(co[j][3] * i1));
    }
}

// ---------------------------------------------------------------------------
// Host launch
// ---------------------------------------------------------------------------
extern "C" void kernel_launch(void* const* d_in, const int* in_sizes, int n_in,
                              void* d_out, int out_size)
{
    const float* x    = (const float*)d_in[0];
    const float* qk_f = (const float*)d_in[1];
    const float* qk_r = (const float*)d_in[2];
    const float* v_f  = (const float*)d_in[3];
    const float* v_r  = (const float*)d_in[4];
    const float* Wgq  = (const float*)d_in[5];
    const float* Wgk  = (const float*)d_in[6];
    const float* Wgv  = (const float*)d_in[7];
    const float* W_O  = (const float*)d_in[8];
    float* out = (float*)d_out;

    float *x32, *bfeat, *cf, *attn, *wo32;
    cudaGetSymbolAddress((void**)&x32,   d_x32);
    cudaGetSymbolAddress((void**)&bfeat, d_Bfeat);
    cudaGetSymbolAddress((void**)&cf,    d_CF);
    cudaGetSymbolAddress((void**)&attn,  d_attn);
    cudaGetSymbolAddress((void**)&wo32,  d_Wo32);

    static bool attrDone = false;
    if (!attrDone) {
        cudaFuncSetAttribute(gemm_w256, cudaFuncAttributeMaxDynamicSharedMemorySize, SMEM_B256);
        cudaFuncSetAttribute(gemm_restore256, cudaFuncAttributeMaxDynamicSharedMemorySize, SMEM_B256);
        cudaFuncSetAttribute(gemm_w128, cudaFuncAttributeMaxDynamicSharedMemorySize, SMEM_B128);
        attrDone = true;
    }

    dim3 t256(256);

    // 0) tf32-round all GEMM operands
    pack_misc<<<(X_ELEMS + 3 * R_ELEMS) / 1024, t256>>>(x, qk_r, v_r, W_O);
    pack_bfeat<<<Dn, t256>>>(Wgq, Wgk, Wgv, qk_f, v_f);

    // 1) Merged logits + features: [2048, 2816] = x32 @ Bfeat  (BN=256)
    gemm_w256<<<dim3(NF / 256, BS / 128, 1), t256, SMEM_B256>>>(
        x32, bfeat, cf, Dn, NF, NF, 0);

    // 2) Softmax + group -> gates
    gate_kernel<<<dim3(BS, 3), t256>>>();

    // 3) Weighted mix -> hQ, hK, hV
    mix_kernel<<<BS, 128>>>();

    // 4) Aeff for Q,K,V (tf32)
    aeff3_kernel<<<BS, t256>>>();

    // 5) Restore: Q,K,V in one launch (z = 0..2), outputs tf32  (BN=256)
    gemm_restore256<<<dim3(Dn / 256, BS / 128, 3), t256, SMEM_B256>>>();

    // 6) Tensor-core causal attention
    flash_mma_kernel<<<dim3(Sn / 64, Bn * NH), 128>>>();

    // 7) Output projection -> d_out  (BN=128 for a fuller wave)
    gemm_w128<<<dim3(Dn / 128, BS / 128, 1), t256, SMEM_B128>>>(
        attn, wo32, out, Dn, Dn, Dn, 0);
}

// round 14
// speedup vs baseline: 1.0066x; 1.0066x over previous
#include <cuda_runtime.h>
#include <math.h>
#include <stdint.h>

// ---------------------------------------------------------------------------
// Problem constants
// ---------------------------------------------------------------------------
#define Bn  2
#define Sn  1024
#define Dn  1024
#define Mn  8
#define Rn  128
#define NNEUR 256
#define NH  16
#define DH  64
#define BS  (Bn * Sn)          // 2048 tokens
#define MR  (Mn * Rn)          // 1024
#define NF  2816               // merged feat width: 768 gate + 1024 qk + 1024 v

// GEMM smem geometry (3-stage cp.async pipeline), templated on BN
#define A_STRIDE 20            // floats per A row (16 data + 4 pad)
#define A_STG (128 * A_STRIDE) // 2560 floats per stage
#define SMEM_B256 (3 * (A_STG + 16 * (256 + 8)) * 4)   // 81408 bytes
#define SMEM_B128 (3 * (A_STG + 16 * (128 + 8)) * 4)   // 56832 bytes

// ---------------------------------------------------------------------------
// Device scratch (allocation-free: __device__ globals)
// ---------------------------------------------------------------------------
__device__ float d_x32[BS * Dn];               // tf32-rounded x
__device__ float d_Bfeat[Dn * NF];             // [Wg_q|Wg_k|Wg_v|qk_f|v_f] tf32
__device__ float d_CF[BS * NF];                // logits(768) + allh_qk + allh_v
__device__ float d_Br[2 * MR * Dn];            // tf32 qk_r ; v_r
__device__ float d_Wo32[Dn * Dn];              // tf32 W_O
__device__ float d_g[3 * BS * Mn];             // grouped gates (q,k,v)
__device__ float d_hq[BS * Rn];
__device__ float d_hk[BS * Rn];
__device__ float d_hv[BS * Rn];
__device__ float d_aeff3[3 * BS * MR];         // (g⊗h) tf32
__device__ float d_QKV[3 * BS * Dn];           // Q ; K ; V (tf32)
__device__ float d_attn[BS * Dn];              // attention out (tf32)

// ---------------------------------------------------------------------------
// TF32 helpers
// ---------------------------------------------------------------------------
__device__ __forceinline__ float to_tf32(float x) {
    uint32_t u;
    asm("cvt.rna.tf32.f32 %0, %1;" : "=r"(u) : "f"(x));
    return __uint_as_float(u);
}

__device__ __forceinline__ void mma_tf32(float c[4], const uint32_t a[4],
                                         uint32_t b0, uint32_t b1) {
    asm volatile(
        "mma.sync.aligned.m16n8k8.row.col.f32.tf32.tf32.f32 "
        "{%0,%1,%2,%3}, {%4,%5,%6,%7}, {%8,%9}, {%0,%1,%2,%3};\n"
        : "+f"(c[0]), "+f"(c[1]), "+f"(c[2]), "+f"(c[3])
        : "r"(a[0]), "r"(a[1]), "r"(a[2]), "r"(a[3]), "r"(b0), "r"(b1));
}

#define CPA(dst, src) \
    asm volatile("cp.async.cg.shared.global [%0], [%1], 16;\n" :: "r"(dst), "l"(src))
#define CPCOMMIT() asm volatile("cp.async.commit_group;\n")
#define CPWAIT2()  asm volatile("cp.async.wait_group 2;\n")

// ---------------------------------------------------------------------------
// TF32 GEMM body, K = 1024 fixed (64 k-tiles of 16). Templated tile width.
// BM=128, BN in {128,256}; 256 threads, 8 warps; warp tile 64 x (BN/4).
// 3-stage cp.async pipeline. Inputs must already be tf32-rounded.
// ---------------------------------------------------------------------------
template <int BN>
__device__ __forceinline__ void
gemm_ca_body(const float* __restrict__ A, const float* __restrict__ B,
             float* __restrict__ C, int lda, int ldb, int ldc, bool cvtOut)
{
    constexpr int BSTR = BN + 8;            // padded B row (floats)
    constexpr int BSTG = 16 * BSTR;         // B stage floats
    constexpr int NJ   = BN / 32;           // n8 tiles per warp (4 or 8)

    extern __shared__ float sm[];
    float* As = sm;                          // 3 stages [128][A_STRIDE]
    float* Bs = sm + 3 * A_STG;              // 3 stages [16][BSTR]

    const int tid  = threadIdx.x;
    const int brow = blockIdx.y * 128;
    const int bcol = blockIdx.x * BN;

    const int warp = tid >> 5;
    const int lane = tid & 31;
    const int wm   = warp >> 2;              // 0..1
    const int wn   = warp & 3;               // 0..3
    const int grp  = lane >> 2;
    const int tg   = lane & 3;
    const int m0   = wm * 64;
    const int n0w  = wn * (BN / 4);

    // A cp.async mapping: 128x16 floats, 2 x 16B per thread
    const int aRow = tid >> 2;               // 0..63
    const int aCol = (tid & 3) << 2;         // 0,4,8,12
    const float* Asrc0 = A + (size_t)(brow + aRow) * lda + aCol;
    const float* Asrc1 = Asrc0 + (size_t)64 * lda;

    // B cp.async mapping: 16xBN floats, BN/64 x 16B per thread
    const int bRow  = tid >> 4;              // 0..15
    const int bCol0 = (tid & 15) << 2;       // 0..60
    const float* Bsrc = B + (size_t)bRow * ldb + bcol + bCol0;

    const uint32_t aBase = (uint32_t)__cvta_generic_to_shared(As);
    const uint32_t bBase = (uint32_t)__cvta_generic_to_shared(Bs);
    const uint32_t sA0 = aBase + (uint32_t)(aRow * A_STRIDE + aCol) * 4;
    const uint32_t sA1 = sA0 + 64 * A_STRIDE * 4;
    const uint32_t sB0 = bBase + (uint32_t)(bRow * BSTR + bCol0) * 4;

#define ISSUE(s_, t_) do {                                                     \
        const uint32_t oa = (uint32_t)(s_) * (A_STG * 4);                      \
        const uint32_t ob = (uint32_t)(s_) * (BSTG * 4);                       \
        CPA(sA0 + oa, Asrc0 + ((t_) << 4));                                    \
        CPA(sA1 + oa, Asrc1 + ((t_) << 4));                                    \
        _Pragma("unroll")                                                      \
        for (int c_ = 0; c_ < BN / 64; c_++)                                   \
            CPA(sB0 + ob + c_ * 256, Bsrc + (size_t)((t_) << 4) * ldb + c_ * 64); \
        CPCOMMIT(); } while (0)

    float c[4][NJ][4];
#pragma unroll
    for (int i = 0; i < 4; i++)
#pragma unroll
        for (int j = 0; j < NJ; j++)
#pragma unroll
            for (int r = 0; r < 4; r++) c[i][j][r] = 0.f;

    ISSUE(0, 0);
    ISSUE(1, 1);
    ISSUE(2, 2);

    for (int t = 0; t < 64; t++) {
        const int s = t % 3;
        CPWAIT2();
        __syncthreads();

        const float* Ast = As + s * A_STG;
        const float* Bst = Bs + s * BSTG;

#pragma unroll
        for (int ks = 0; ks < 2; ks++) {
            const int kb = ks << 3;
            uint32_t af[4][4], bf[NJ][2];
#pragma unroll
            for (int i = 0; i < 4; i++) {
                const int r0 = (m0 + i * 16 + grp) * A_STRIDE;
                af[i][0] = __float_as_uint(Ast[r0 + kb + tg]);
                af[i][1] = __float_as_uint(Ast[r0 + 8 * A_STRIDE + kb + tg]);
                af[i][2] = __float_as_uint(Ast[r0 + kb + tg + 4]);
                af[i][3] = __float_as_uint(Ast[r0 + 8 * A_STRIDE + kb + tg + 4]);
            }
#pragma unroll
            for (int j = 0; j < NJ; j++) {
                const int n0 = n0w + j * 8 + grp;
                bf[j][0] = __float_as_uint(Bst[(kb + tg) * BSTR + n0]);
                bf[j][1] = __float_as_uint(Bst[(kb + tg + 4) * BSTR + n0]);
            }
#pragma unroll
            for (int i = 0; i < 4; i++)
#pragma unroll
                for (int j = 0; j < NJ; j++)
                    mma_tf32(c[i][j], af[i], bf[j][0], bf[j][1]);
        }

        __syncthreads();
        if (t + 3 < 64) ISSUE(s, t + 3); else CPCOMMIT();
    }
#undef ISSUE

#pragma unroll
    for (int i = 0; i < 4; i++) {
        const int r0 = brow + m0 + i * 16 + grp;
#pragma unroll
        for (int j = 0; j < NJ; j++) {
            const int cc = bcol + n0w + j * 8 + tg * 2;
            float v0 = c[i][j][0], v1 = c[i][j][1], v2 = c[i][j][2], v3 = c[i][j][3];
            if (cvtOut) {
                v0 = to_tf32(v0); v1 = to_tf32(v1);
                v2 = to_tf32(v2); v3 = to_tf32(v3);
            }
            *(float2*)&C[(size_t)r0 * ldc + cc]       = make_float2(v0, v1);
            *(float2*)&C[(size_t)(r0 + 8) * ldc + cc] = make_float2(v2, v3);
        }
    }
}

// -------- GEMM wrappers ----------------------------------------------------
__global__ void __launch_bounds__(256, 1)
gemm_w256(const float* __restrict__ A, const float* __restrict__ B,
          float* __restrict__ C, int lda, int ldb, int ldc, int cvtOut)
{
    gemm_ca_body<256>(A, B, C, lda, ldb, ldc, cvtOut != 0);
}

__global__ void __launch_bounds__(256, 2)
gemm_w128(const float* __restrict__ A, const float* __restrict__ B,
          float* __restrict__ C, int lda, int ldb, int ldc, int cvtOut)
{
    gemm_ca_body<128>(A, B, C, lda, ldb, ldc, cvtOut != 0);
}

// restore: z 0..2 -> Q (qk_r), K (qk_r), V (v_r); outputs tf32-rounded
__global__ void __launch_bounds__(256, 1)
gemm_restore256()
{
    const int z = blockIdx.z;
    const float* A = d_aeff3 + (size_t)z * BS * MR;
    const float* B = d_Br + (z < 2 ? 0 : (size_t)MR * Dn);
    float* C = d_QKV + (size_t)z * BS * Dn;
    gemm_ca_body<256>(A, B, C, MR, Dn, Dn, true);
}

// ---------------------------------------------------------------------------
// pack_misc: tf32-round x, qk_r, v_r, W_O (float4 per thread)
// ---------------------------------------------------------------------------
#define X_ELEMS  (BS * Dn)          // 2097152
#define R_ELEMS  (MR * Dn)          // 1048576
__global__ void pack_misc(const float* __restrict__ x, const float* __restrict__ qk_r,
                          const float* __restrict__ v_r, const float* __restrict__ wo)
{
    const size_t i4 = ((size_t)blockIdx.x * 256 + threadIdx.x) * 4;
    const float* src;
    float* dst;
    size_t off;
    if (i4 < X_ELEMS)                     { src = x;    dst = d_x32;            off = i4; }
    else if (i4 < X_ELEMS + R_ELEMS)      { src = qk_r; dst = d_Br;             off = i4 - X_ELEMS; }
    else if (i4 < X_ELEMS + 2 * R_ELEMS)  { src = v_r;  dst = d_Br + R_ELEMS;   off = i4 - X_ELEMS - R_ELEMS; }
    else                                  { src = wo;   dst = d_Wo32;           off = i4 - X_ELEMS - 2 * R_ELEMS; }
    float4 v = *(const float4*)(src + off);
    *(float4*)(dst + off) = make_float4(to_tf32(v.x), to_tf32(v.y),
                                        to_tf32(v.z), to_tf32(v.w));
}

// ---------------------------------------------------------------------------
// pack_bfeat: build [D][2816] = [Wg_q|Wg_k|Wg_v|qk_f(m-major cols)|v_f]
// ---------------------------------------------------------------------------
__global__ void pack_bfeat(const float* __restrict__ wq, const float* __restrict__ wk,
                           const float* __restrict__ wv, const float* __restrict__ qkf,
                           const float* __restrict__ vf)
{
    const int d = blockIdx.x;
    for (int col = threadIdx.x; col < NF; col += 256) {
        float v;
        if (col < 768) {
            const int which = col >> 8;
            const int n = col & 255;
            const float* w = (which == 0) ? wq : (which == 1) ? wk : wv;
            v = w[(size_t)d * NNEUR + n];
        } else if (col < 1792) {
            const int cc = col - 768;
            v = qkf[((size_t)(cc >> 7) * Dn + d) * Rn + (cc & 127)];
        } else {
            const int cc = col - 1792;
            v = vf[((size_t)(cc >> 7) * Dn + d) * Rn + (cc & 127)];
        }
        d_Bfeat[(size_t)d * NF + col] = to_tf32(v);
    }
}

// ---------------------------------------------------------------------------
// Gate softmax + grouping. Reads logits from d_CF (stride NF). grid=(BS,3).
// ---------------------------------------------------------------------------
__global__ void gate_kernel()
{
    const int token = blockIdx.x;
    const int which = blockIdx.y;
    const float* lp = d_CF + (size_t)token * NF + which * NNEUR;
    const int t = threadIdx.x;

    __shared__ float red[256];
    __shared__ float gs[8];

    float v = lp[t];
    red[t] = v; __syncthreads();
#pragma unroll
    for (int s = 128; s > 0; s >>= 1) {
        if (t < s) red[t] = fmaxf(red[t], red[t + s]);
        __syncthreads();
    }
    float mx = red[0];
    __syncthreads();

    float e = __expf(v - mx);
#pragma unroll
    for (int off = 16; off; off >>= 1)
        e += __shfl_down_sync(0xffffffffu, e, off);
    if ((t & 31) == 0) gs[t >> 5] = e;
    __syncthreads();

    if (t < 8) {
        float tot = 0.f;
#pragma unroll
        for (int i = 0; i < 8; i++) tot += gs[i];
        d_g[((size_t)which * BS + token) * Mn + t] = gs[t] / (tot * (1.0f + 1e-8f));
    }
}

// ---------------------------------------------------------------------------
// Mix: h[bs,r] = sum_m g[bs,m] * allh[bs,m,r]  (allh lives in d_CF cols 768+)
// ---------------------------------------------------------------------------
__global__ void mix_kernel()
{
    const int bs = blockIdx.x;
    const int r  = threadIdx.x;
    const float* gq = d_g + (size_t)bs * Mn;
    const float* gk = d_g + (size_t)BS * Mn + (size_t)bs * Mn;
    const float* gv = d_g + (size_t)2 * BS * Mn + (size_t)bs * Mn;
    const float* row = d_CF + (size_t)bs * NF;

    float hq = 0.f, hk = 0.f, hv = 0.f;
#pragma unroll
    for (int m = 0; m < Mn; m++) {
        float a  = row[768 + m * Rn + r];
        float av = row[1792 + m * Rn + r];
        hq = fmaf(gq[m], a, hq);
        hk = fmaf(gk[m], a, hk);
        hv = fmaf(gv[m], av, hv);
    }
    d_hq[bs * Rn + r] = hq;
    d_hk[bs * Rn + r] = hk;
    d_hv[bs * Rn + r] = hv;
}

// ---------------------------------------------------------------------------
// Aeff3[z][bs, m*R+r] = tf32(g_z[bs,m]*h_z[bs,r])
// ---------------------------------------------------------------------------
__global__ void aeff3_kernel()
{
    const int bs = blockIdx.x;
    const int cidx = threadIdx.x * 4;
    const int m = cidx >> 7;

    const float gq = d_g[(size_t)bs * Mn + m];
    const float gk = d_g[(size_t)BS * Mn + (size_t)bs * Mn + m];
    const float gv = d_g[(size_t)2 * BS * Mn + (size_t)bs * Mn + m];

    const int r = cidx & 127;
    float4 hq4 = *(const float4*)(d_hq + (size_t)bs * Rn + r);
    float4 hk4 = *(const float4*)(d_hk + (size_t)bs * Rn + r);
    float4 hv4 = *(const float4*)(d_hv + (size_t)bs * Rn + r);

    *(float4*)(d_aeff3 + (size_t)bs * MR + cidx) =
        make_float4(to_tf32(gq * hq4.x), to_tf32(gq * hq4.y),
                    to_tf32(gq * hq4.z), to_tf32(gq * hq4.w));
    *(float4*)(d_aeff3 + (size_t)BS * MR + (size_t)bs * MR + cidx) =
        make_float4(to_tf32(gk * hk4.x), to_tf32(gk * hk4.y),
                    to_tf32(gk * hk4.z), to_tf32(gk * hk4.w));
    *(float4*)(d_aeff3 + (size_t)2 * BS * MR + (size_t)bs * MR + cidx) =
        make_float4(to_tf32(gv * hv4.x), to_tf32(gv * hv4.y),
                    to_tf32(gv * hv4.z), to_tf32(gv * hv4.w));
}

// ---------------------------------------------------------------------------
// Tensor-core causal flash attention (TF32 m16n8k8). Q/K/V pre-rounded.
// Block 128 threads (4 warps), 64 query rows. Grid (S/64, B*NH).
// ---------------------------------------------------------------------------
__global__ void __launch_bounds__(128, 3)
flash_mma_kernel()
{
    __shared__ float Ks[64][68];
    __shared__ float Vs[64][72];

    const int tid  = threadIdx.x;
    const int warp = tid >> 5;
    const int lane = tid & 31;
    const int grp  = lane >> 2;
    const int tg   = lane & 3;
    const int qb   = blockIdx.x;
    const int bh   = blockIdx.y;
    const int b    = bh >> 4;
    const int h    = bh & 15;
    const int q0   = qb * 64;
    const int m0   = warp * 16;

    const float* Qg = d_QKV;
    const float* Kg = d_QKV + (size_t)BS * Dn;
    const float* Vg = d_QKV + (size_t)2 * BS * Dn;

    // stage Q tile (scale by 1/8 — exact power of two, stays tf32)
#pragma unroll
    for (int i = 0; i < 8; i++) {
        int idx = tid + i * 128;
        int row = idx >> 4, c = (idx & 15) * 4;
        float4 v = *(const float4*)(Qg + (size_t)(b * Sn + q0 + row) * Dn + h * DH + c);
        *(float4*)&Ks[row][c] = make_float4(v.x * 0.125f, v.y * 0.125f,
                                            v.z * 0.125f, v.w * 0.125f);
    }
    __syncthreads();

    uint32_t qf[8][4];
#pragma unroll
    for (int dk = 0; dk < 8; dk++) {
        qf[dk][0] = __float_as_uint(Ks[m0 + grp][dk * 8 + tg]);
        qf[dk][1] = __float_as_uint(Ks[m0 + grp + 8][dk * 8 + tg]);
        qf[dk][2] = __float_as_uint(Ks[m0 + grp][dk * 8 + tg + 4]);
        qf[dk][3] = __float_as_uint(Ks[m0 + grp + 8][dk * 8 + tg + 4]);
    }
    __syncthreads();

    float co[8][4];
#pragma unroll
    for (int j = 0; j < 8; j++)
#pragma unroll
        for (int r = 0; r < 4; r++) co[j][r] = 0.f;
    float mr0 = -1e30f, mr1 = -1e30f, l0 = 0.f, l1 = 0.f;

    for (int kt = 0; kt <= qb; kt++) {
        const int k0 = kt * 64;

#pragma unroll
        for (int i = 0; i < 8; i++) {
            int idx = tid + i * 128;
            int row = idx >> 4, c = (idx & 15) * 4;
            size_t g = (size_t)(b * Sn + k0 + row) * Dn + h * DH + c;
            *(float4*)&Ks[row][c] = *(const float4*)(Kg + g);
            *(float4*)&Vs[row][c] = *(const float4*)(Vg + g);
        }
        __syncthreads();

        float cs[8][4];
#pragma unroll
        for (int j = 0; j < 8; j++) {
#pragma unroll
            for (int r = 0; r < 4; r++) cs[j][r] = 0.f;
#pragma unroll
            for (int dk = 0; dk < 8; dk++) {
                uint32_t b0 = __float_as_uint(Ks[j * 8 + grp][dk * 8 + tg]);
                uint32_t b1 = __float_as_uint(Ks[j * 8 + grp][dk * 8 + tg + 4]);
                mma_tf32(cs[j], qf[dk], b0, b1);
            }
        }

        if (kt == qb) {
            const int r0 = q0 + m0 + grp;
            const int r1 = r0 + 8;
#pragma unroll
            for (int j = 0; j < 8; j++) {
                const int ca = k0 + j * 8 + 2 * tg;
                if (ca > r0)     cs[j][0] = -1e30f;
                if (ca + 1 > r0) cs[j][1] = -1e30f;
                if (ca > r1)     cs[j][2] = -1e30f;
                if (ca + 1 > r1) cs[j][3] = -1e30f;
            }
        }

        float mx0 = mr0, mx1 = mr1;
#pragma unroll
        for (int j = 0; j < 8; j++) {
            mx0 = fmaxf(mx0, fmaxf(cs[j][0], cs[j][1]));
            mx1 = fmaxf(mx1, fmaxf(cs[j][2], cs[j][3]));
        }
        mx0 = fmaxf(mx0, __shfl_xor_sync(0xffffffffu, mx0, 1));
        mx0 = fmaxf(mx0, __shfl_xor_sync(0xffffffffu, mx0, 2));
        mx1 = fmaxf(mx1, __shfl_xor_sync(0xffffffffu, mx1, 1));
        mx1 = fmaxf(mx1, __shfl_xor_sync(0xffffffffu, mx1, 2));

        float corr0 = __expf(mr0 - mx0);
        float corr1 = __expf(mr1 - mx1);
        mr0 = mx0; mr1 = mx1;

        float s0 = 0.f, s1 = 0.f;
#pragma unroll
        for (int j = 0; j < 8; j++) {
            cs[j][0] = __expf(cs[j][0] - mx0); s0 += cs[j][0];
            cs[j][1] = __expf(cs[j][1] - mx0); s0 += cs[j][1];
            cs[j][2] = __expf(cs[j][2] - mx1); s1 += cs[j][2];
            cs[j][3] = __expf(cs[j][3] - mx1); s1 += cs[j][3];
        }
        s0 += __shfl_xor_sync(0xffffffffu, s0, 1);
        s0 += __shfl_xor_sync(0xffffffffu, s0, 2);
        s1 += __shfl_xor_sync(0xffffffffu, s1, 1);
        s1 += __shfl_xor_sync(0xffffffffu, s1, 2);
        l0 = l0 * corr0 + s0;
        l1 = l1 * corr1 + s1;

#pragma unroll
        for (int j = 0; j < 8; j++) {
            co[j][0] *= corr0; co[j][1] *= corr0;
            co[j][2] *= corr1; co[j][3] *= corr1;
        }

        const int base = lane & ~3;
        const int s1l = base + (tg >> 1);
        const int s2l = s1l + 2;
        const bool odd = tg & 1;
#pragma unroll
        for (int kk = 0; kk < 8; kk++) {
            float v00 = __shfl_sync(0xffffffffu, cs[kk][0], s1l);
            float v01 = __shfl_sync(0xffffffffu, cs[kk][1], s1l);
            float v02 = __shfl_sync(0xffffffffu, cs[kk][0], s2l);
            float v03 = __shfl_sync(0xffffffffu, cs[kk][1], s2l);
            float v10 = __shfl_sync(0xffffffffu, cs[kk][2], s1l);
            float v11 = __shfl_sync(0xffffffffu, cs[kk][3], s1l);
            float v12 = __shfl_sync(0xffffffffu, cs[kk][2], s2l);
            float v13 = __shfl_sync(0xffffffffu, cs[kk][3], s2l);
            uint32_t ap[4];
            ap[0] = __float_as_uint(to_tf32(odd ? v01 : v00));
            ap[1] = __float_as_uint(to_tf32(odd ? v11 : v10));
            ap[2] = __float_as_uint(to_tf32(odd ? v03 : v02));
            ap[3] = __float_as_uint(to_tf32(odd ? v13 : v12));
#pragma unroll
            for (int j = 0; j < 8; j++) {
                uint32_t b0 = __float_as_uint(Vs[kk * 8 + tg][j * 8 + grp]);
                uint32_t b1 = __float_as_uint(Vs[kk * 8 + tg + 4][j * 8 + grp]);
                mma_tf32(co[j], ap, b0, b1);
            }
        }
        __syncthreads();
    }

    const float i0 = 1.f / l0;
    const float i1 = 1.f / l1;
    const int r0 = q0 + m0 + grp;
    float* op0 = d_attn + (size_t)(b * Sn + r0) * Dn + h * DH;
    float* op1 = d_attn + (size_t)(b * Sn + r0 + 8) * Dn + h * DH;
#pragma unroll
    for (int j = 0; j < 8; j++) {
        const int cc = j * 8 + 2 * tg;
        *(float2*)(op0 + cc) = make_float2(to_tf32(co[j][0] * i0), to_tf32(co[j][1] * i0));
        *(float2*)(op1 + cc) = make_float2(to_tf32(co[j][2] * i1), to_tf32(co[j][3] * i1));
    }
}

// ---------------------------------------------------------------------------
// Host launch
// ---------------------------------------------------------------------------
extern "C" void kernel_launch(void* const* d_in, const int* in_sizes, int n_in,
                              void* d_out, int out_size)
{
    const float* x    = (const float*)d_in[0];
    const float* qk_f = (const float*)d_in[1];
    const float* qk_r = (const float*)d_in[2];
    const float* v_f  = (const float*)d_in[3];
    const float* v_r  = (const float*)d_in[4];
    const float* Wgq  = (const float*)d_in[5];
    const float* Wgk  = (const float*)d_in[6];
    const float* Wgv  = (const float*)d_in[7];
    const float* W_O  = (const float*)d_in[8];
    float* out = (float*)d_out;

    float *x32, *bfeat, *cf, *attn, *wo32;
    cudaGetSymbolAddress((void**)&x32,   d_x32);
    cudaGetSymbolAddress((void**)&bfeat, d_Bfeat);
    cudaGetSymbolAddress((void**)&cf,    d_CF);
    cudaGetSymbolAddress((void**)&attn,  d_attn);
    cudaGetSymbolAddress((void**)&wo32,  d_Wo32);

    static bool attrDone = false;
    if (!attrDone) {
        cudaFuncSetAttribute(gemm_w256, cudaFuncAttributeMaxDynamicSharedMemorySize, SMEM_B256);
        cudaFuncSetAttribute(gemm_restore256, cudaFuncAttributeMaxDynamicSharedMemorySize, SMEM_B256);
        cudaFuncSetAttribute(gemm_w128, cudaFuncAttributeMaxDynamicSharedMemorySize, SMEM_B128);
        attrDone = true;
    }

    dim3 t256(256);

    // 0) tf32-round all GEMM operands
    pack_misc<<<(X_ELEMS + 3 * R_ELEMS) / 1024, t256>>>(x, qk_r, v_r, W_O);
    pack_bfeat<<<Dn, t256>>>(Wgq, Wgk, Wgv, qk_f, v_f);

    // 1) Merged logits + features: [2048, 2816] = x32 @ Bfeat  (BN=256)
    gemm_w256<<<dim3(NF / 256, BS / 128, 1), t256, SMEM_B256>>>(
        x32, bfeat, cf, Dn, NF, NF, 0);

    // 2) Softmax + group -> gates
    gate_kernel<<<dim3(BS, 3), t256>>>();

    // 3) Weighted mix -> hQ, hK, hV
    mix_kernel<<<BS, 128>>>();

    // 4) Aeff for Q,K,V (tf32)
    aeff3_kernel<<<BS, t256>>>();

    // 5) Restore: Q,K,V in one launch (z = 0..2), outputs tf32  (BN=256)
    gemm_restore256<<<dim3(Dn / 256, BS / 128, 3), t256, SMEM_B256>>>();

    // 6) Tensor-core causal attention
    flash_mma_kernel<<<dim3(Sn / 64, Bn * NH), 128>>>();

    // 7) Output projection -> d_out  (BN=128 for a fuller wave)
    gemm_w128<<<dim3(Dn / 128, BS / 128, 1), t256, SMEM_B128>>>(
        attn, wo32, out, Dn, Dn, Dn, 0);
}

// round 15
// speedup vs baseline: 1.1417x; 1.1342x over previous
#include <cuda_runtime.h>
#include <math.h>
#include <stdint.h>

// ---------------------------------------------------------------------------
// Problem constants
// ---------------------------------------------------------------------------
#define Bn  2
#define Sn  1024
#define Dn  1024
#define Mn  8
#define Rn  128
#define NNEUR 256
#define NH  16
#define DH  64
#define BS  (Bn * Sn)          // 2048 tokens
#define MR  (Mn * Rn)          // 1024
#define NF  2816               // merged feat width: 768 gate + 1024 qk + 1024 v

// GEMM smem geometry (4-stage cp.async pipeline, BN=128)
#define A_STRIDE 20            // floats per A row (16 data + 4 pad)
#define B_STRIDE 136           // floats per B row (128 data + 8 pad)
#define A_STG (128 * A_STRIDE) // 2560 floats per stage
#define B_STG (16 * B_STRIDE)  // 2176 floats per stage
#define SMEM_BYTES (4 * (A_STG + B_STG) * 4)   // 75776 bytes

// ---------------------------------------------------------------------------
// Device scratch (allocation-free: __device__ globals)
// ---------------------------------------------------------------------------
__device__ float d_x32[BS * Dn];               // tf32-rounded x
__device__ float d_Bfeat[Dn * NF];             // [Wg_q|Wg_k|Wg_v|qk_f|v_f] tf32
__device__ float d_CF[BS * NF];                // logits(768) + allh_qk + allh_v
__device__ float d_Br[2 * MR * Dn];            // tf32 qk_r ; v_r
__device__ float d_Wo32[Dn * Dn];              // tf32 W_O
__device__ float d_g[3 * BS * Mn];             // grouped gates (q,k,v)
__device__ float d_hq[BS * Rn];
__device__ float d_hk[BS * Rn];
__device__ float d_hv[BS * Rn];
__device__ float d_aeff3[3 * BS * MR];         // (g⊗h) tf32
__device__ float d_QKV[3 * BS * Dn];           // Q ; K ; V (tf32)
__device__ float d_attn[BS * Dn];              // attention out (tf32)

// ---------------------------------------------------------------------------
// TF32 helpers
// ---------------------------------------------------------------------------
__device__ __forceinline__ float to_tf32(float x) {
    uint32_t u;
    asm("cvt.rna.tf32.f32 %0, %1;" : "=r"(u) : "f"(x));
    return __uint_as_float(u);
}

__device__ __forceinline__ void mma_tf32(float c[4], const uint32_t a[4],
                                         uint32_t b0, uint32_t b1) {
    asm volatile(
        "mma.sync.aligned.m16n8k8.row.col.f32.tf32.tf32.f32 "
        "{%0,%1,%2,%3}, {%4,%5,%6,%7}, {%8,%9}, {%0,%1,%2,%3};\n"
        : "+f"(c[0]), "+f"(c[1]), "+f"(c[2]), "+f"(c[3])
        : "r"(a[0]), "r"(a[1]), "r"(a[2]), "r"(a[3]), "r"(b0), "r"(b1));
}

#define CPA(dst, src) \
    asm volatile("cp.async.cg.shared.global [%0], [%1], 16;\n" :: "r"(dst), "l"(src))
#define CPCOMMIT() asm volatile("cp.async.commit_group;\n")
#define CPWAIT2()  asm volatile("cp.async.wait_group 2;\n")

// ---------------------------------------------------------------------------
// TF32 GEMM body, K = 1024 fixed (64 k-tiles of 16).
// BM=BN=128, 256 threads (8 warps, warp tile 64x32).
// 4-stage cp.async pipeline, ONE __syncthreads per k-tile:
//   at iter t: read stage t&3, write stage (t+3)&3 (disjoint); the stage being
//   written was last read at t-1, complete for all warps past the barrier.
// Inputs must already be tf32-rounded (hot loop does no conversion).
// ---------------------------------------------------------------------------
__device__ __forceinline__ void
gemm_ca_body(const float* __restrict__ A, const float* __restrict__ B,
             float* __restrict__ C, int lda, int ldb, int ldc, bool cvtOut)
{
    extern __shared__ float sm[];
    float* As = sm;                    // 4 stages [128][A_STRIDE]
    float* Bs = sm + 4 * A_STG;        // 4 stages [16][B_STRIDE]

    const int tid  = threadIdx.x;
    const int brow = blockIdx.y * 128;
    const int bcol = blockIdx.x * 128;

    const int warp = tid >> 5;
    const int lane = tid & 31;
    const int wm   = warp >> 2;
    const int wn   = warp & 3;
    const int grp  = lane >> 2;
    const int tg   = lane & 3;
    const int m0   = wm * 64;

    // cp.async source / dest mapping (2 x 16B chunks per thread per matrix)
    const int aRow = tid >> 2;               // 0..63
    const int aCol = (tid & 3) << 2;         // 0,4,8,12
    const float* Asrc0 = A + (size_t)(brow + aRow) * lda + aCol;
    const float* Asrc1 = Asrc0 + (size_t)64 * lda;

    const int bRow = tid >> 5;               // 0..7
    const int bCol = (tid & 31) << 2;        // 0..124
    const float* Bsrc0 = B + (size_t)bRow * ldb + bcol + bCol;
    const float* Bsrc1 = Bsrc0 + (size_t)8 * ldb;

    const uint32_t aBase = (uint32_t)__cvta_generic_to_shared(As);
    const uint32_t bBase = (uint32_t)__cvta_generic_to_shared(Bs);
    const uint32_t sA0 = aBase + (uint32_t)(aRow * A_STRIDE + aCol) * 4;
    const uint32_t sA1 = sA0 + 64 * A_STRIDE * 4;
    const uint32_t sB0 = bBase + (uint32_t)(bRow * B_STRIDE + bCol) * 4;
    const uint32_t sB1 = sB0 + 8 * B_STRIDE * 4;

#define ISSUE(s_, t_) do {                                        \
        const uint32_t oa = (uint32_t)(s_) * (A_STG * 4);          \
        const uint32_t ob = (uint32_t)(s_) * (B_STG * 4);          \
        CPA(sA0 + oa, Asrc0 + ((t_) << 4));                        \
        CPA(sA1 + oa, Asrc1 + ((t_) << 4));                        \
        CPA(sB0 + ob, Bsrc0 + (size_t)((t_) << 4) * ldb);          \
        CPA(sB1 + ob, Bsrc1 + (size_t)((t_) << 4) * ldb);          \
        CPCOMMIT(); } while (0)

    float c[4][4][4];
#pragma unroll
    for (int i = 0; i < 4; i++)
#pragma unroll
        for (int j = 0; j < 4; j++)
#pragma unroll
            for (int r = 0; r < 4; r++) c[i][j][r] = 0.f;

    ISSUE(0, 0);
    ISSUE(1, 1);
    ISSUE(2, 2);

    for (int t = 0; t < 64; t++) {
        const int s = t & 3;
        CPWAIT2();
        __syncthreads();

        // prefetch 3 tiles ahead into the stage retired at t-1
        if (t + 3 < 64) ISSUE((t + 3) & 3, t + 3);

        const float* Ast = As + s * A_STG;
        const float* Bst = Bs + s * B_STG;

#pragma unroll
        for (int ks = 0; ks < 2; ks++) {
            const int kb = ks << 3;
            uint32_t af[4][4], bf[4][2];
#pragma unroll
            for (int i = 0; i < 4; i++) {
                const int r0 = (m0 + i * 16 + grp) * A_STRIDE;
                af[i][0] = __float_as_uint(Ast[r0 + kb + tg]);
                af[i][1] = __float_as_uint(Ast[r0 + 8 * A_STRIDE + kb + tg]);
                af[i][2] = __float_as_uint(Ast[r0 + kb + tg + 4]);
                af[i][3] = __float_as_uint(Ast[r0 + 8 * A_STRIDE + kb + tg + 4]);
            }
#pragma unroll
            for (int j = 0; j < 4; j++) {
                const int n0 = wn * 32 + j * 8 + grp;
                bf[j][0] = __float_as_uint(Bst[(kb + tg) * B_STRIDE + n0]);
                bf[j][1] = __float_as_uint(Bst[(kb + tg + 4) * B_STRIDE + n0]);
            }
#pragma unroll
            for (int i = 0; i < 4; i++)
#pragma unroll
                for (int j = 0; j < 4; j++)
                    mma_tf32(c[i][j], af[i], bf[j][0], bf[j][1]);
        }
    }
#undef ISSUE

#pragma unroll
    for (int i = 0; i < 4; i++) {
        const int r0 = brow + m0 + i * 16 + grp;
#pragma unroll
        for (int j = 0; j < 4; j++) {
            const int cc = bcol + wn * 32 + j * 8 + tg * 2;
            float v0 = c[i][j][0], v1 = c[i][j][1], v2 = c[i][j][2], v3 = c[i][j][3];
            if (cvtOut) {
                v0 = to_tf32(v0); v1 = to_tf32(v1);
                v2 = to_tf32(v2); v3 = to_tf32(v3);
            }
            *(float2*)&C[(size_t)r0 * ldc + cc]       = make_float2(v0, v1);
            *(float2*)&C[(size_t)(r0 + 8) * ldc + cc] = make_float2(v2, v3);
        }
    }
}

// -------- GEMM wrappers ----------------------------------------------------
__global__ void __launch_bounds__(256, 2)
gemm_ca(const float* __restrict__ A, const float* __restrict__ B,
        float* __restrict__ C, int lda, int ldb, int ldc, int cvtOut)
{
    gemm_ca_body(A, B, C, lda, ldb, ldc, cvtOut != 0);
}

// restore: z 0..2 -> Q (qk_r), K (qk_r), V (v_r); outputs tf32-rounded
__global__ void __launch_bounds__(256, 2)
gemm_restore_ca()
{
    const int z = blockIdx.z;
    const float* A = d_aeff3 + (size_t)z * BS * MR;
    const float* B = d_Br + (z < 2 ? 0 : (size_t)MR * Dn);
    float* C = d_QKV + (size_t)z * BS * Dn;
    gemm_ca_body(A, B, C, MR, Dn, Dn, true);
}

// ---------------------------------------------------------------------------
// pack_misc: tf32-round x, qk_r, v_r, W_O (float4 per thread)
// ---------------------------------------------------------------------------
#define X_ELEMS  (BS * Dn)          // 2097152
#define R_ELEMS  (MR * Dn)          // 1048576
__global__ void pack_misc(const float* __restrict__ x, const float* __restrict__ qk_r,
                          const float* __restrict__ v_r, const float* __restrict__ wo)
{
    const size_t i4 = ((size_t)blockIdx.x * 256 + threadIdx.x) * 4;
    const float* src;
    float* dst;
    size_t off;
    if (i4 < X_ELEMS)                     { src = x;    dst = d_x32;            off = i4; }
    else if (i4 < X_ELEMS + R_ELEMS)      { src = qk_r; dst = d_Br;             off = i4 - X_ELEMS; }
    else if (i4 < X_ELEMS + 2 * R_ELEMS)  { src = v_r;  dst = d_Br + R_ELEMS;   off = i4 - X_ELEMS - R_ELEMS; }
    else                                  { src = wo;   dst = d_Wo32;           off = i4 - X_ELEMS - 2 * R_ELEMS; }
    float4 v = *(const float4*)(src + off);
    *(float4*)(dst + off) = make_float4(to_tf32(v.x), to_tf32(v.y),
                                        to_tf32(v.z), to_tf32(v.w));
}

// ---------------------------------------------------------------------------
// pack_bfeat: build [D][2816] = [Wg_q|Wg_k|Wg_v|qk_f(m-major cols)|v_f]
// ---------------------------------------------------------------------------
__global__ void pack_bfeat(const float* __restrict__ wq, const float* __restrict__ wk,
                           const float* __restrict__ wv, const float* __restrict__ qkf,
                           const float* __restrict__ vf)
{
    const int d = blockIdx.x;
    for (int col = threadIdx.x; col < NF; col += 256) {
        float v;
        if (col < 768) {
            const int which = col >> 8;
            const int n = col & 255;
            const float* w = (which == 0) ? wq : (which == 1) ? wk : wv;
            v = w[(size_t)d * NNEUR + n];
        } else if (col < 1792) {
            const int cc = col - 768;
            v = qkf[((size_t)(cc >> 7) * Dn + d) * Rn + (cc & 127)];
        } else {
            const int cc = col - 1792;
            v = vf[((size_t)(cc >> 7) * Dn + d) * Rn + (cc & 127)];
        }
        d_Bfeat[(size_t)d * NF + col] = to_tf32(v);
    }
}

// ---------------------------------------------------------------------------
// Gate softmax + grouping. Reads logits from d_CF (stride NF). grid=(BS,3).
// ---------------------------------------------------------------------------
__global__ void gate_kernel()
{
    const int token = blockIdx.x;
    const int which = blockIdx.y;
    const float* lp = d_CF + (size_t)token * NF + which * NNEUR;
    const int t = threadIdx.x;

    __shared__ float red[256];
    __shared__ float gs[8];

    float v = lp[t];
    red[t] = v; __syncthreads();
#pragma unroll
    for (int s = 128; s > 0; s >>= 1) {
        if (t < s) red[t] = fmaxf(red[t], red[t + s]);
        __syncthreads();
    }
    float mx = red[0];
    __syncthreads();

    float e = __expf(v - mx);
#pragma unroll
    for (int off = 16; off; off >>= 1)
        e += __shfl_down_sync(0xffffffffu, e, off);
    if ((t & 31) == 0) gs[t >> 5] = e;
    __syncthreads();

    if (t < 8) {
        float tot = 0.f;
#pragma unroll
        for (int i = 0; i < 8; i++) tot += gs[i];
        d_g[((size_t)which * BS + token) * Mn + t] = gs[t] / (tot * (1.0f + 1e-8f));
    }
}

// ---------------------------------------------------------------------------
// Mix: h[bs,r] = sum_m g[bs,m] * allh[bs,m,r]  (allh lives in d_CF cols 768+)
// ---------------------------------------------------------------------------
__global__ void mix_kernel()
{
    const int bs = blockIdx.x;
    const int r  = threadIdx.x;
    const float* gq = d_g + (size_t)bs * Mn;
    const float* gk = d_g + (size_t)BS * Mn + (size_t)bs * Mn;
    const float* gv = d_g + (size_t)2 * BS * Mn + (size_t)bs * Mn;
    const float* row = d_CF + (size_t)bs * NF;

    float hq = 0.f, hk = 0.f, hv = 0.f;
#pragma unroll
    for (int m = 0; m < Mn; m++) {
        float a  = row[768 + m * Rn + r];
        float av = row[1792 + m * Rn + r];
        hq = fmaf(gq[m], a, hq);
        hk = fmaf(gk[m], a, hk);
        hv = fmaf(gv[m], av, hv);
    }
    d_hq[bs * Rn + r] = hq;
    d_hk[bs * Rn + r] = hk;
    d_hv[bs * Rn + r] = hv;
}

// ---------------------------------------------------------------------------
// Aeff3[z][bs, m*R+r] = tf32(g_z[bs,m]*h_z[bs,r])
// ---------------------------------------------------------------------------
__global__ void aeff3_kernel()
{
    const int bs = blockIdx.x;
    const int cidx = threadIdx.x * 4;
    const int m = cidx >> 7;

    const float gq = d_g[(size_t)bs * Mn + m];
    const float gk = d_g[(size_t)BS * Mn + (size_t)bs * Mn + m];
    const float gv = d_g[(size_t)2 * BS * Mn + (size_t)bs * Mn + m];

    const int r = cidx & 127;
    float4 hq4 = *(const float4*)(d_hq + (size_t)bs * Rn + r);
    float4 hk4 = *(const float4*)(d_hk + (size_t)bs * Rn + r);
    float4 hv4 = *(const float4*)(d_hv + (size_t)bs * Rn + r);

    *(float4*)(d_aeff3 + (size_t)bs * MR + cidx) =
        make_float4(to_tf32(gq * hq4.x), to_tf32(gq * hq4.y),
                    to_tf32(gq * hq4.z), to_tf32(gq * hq4.w));
    *(float4*)(d_aeff3 + (size_t)BS * MR + (size_t)bs * MR + cidx) =
        make_float4(to_tf32(gk * hk4.x), to_tf32(gk * hk4.y),
                    to_tf32(gk * hk4.z), to_tf32(gk * hk4.w));
    *(float4*)(d_aeff3 + (size_t)2 * BS * MR + (size_t)bs * MR + cidx) =
        make_float4(to_tf32(gv * hv4.x), to_tf32(gv * hv4.y),
                    to_tf32(gv * hv4.z), to_tf32(gv * hv4.w));
}

// ---------------------------------------------------------------------------
// Tensor-core causal flash attention (TF32 m16n8k8). Q/K/V pre-rounded.
// Block 128 threads (4 warps), 64 query rows. Grid (S/64, B*NH).
// ---------------------------------------------------------------------------
__global__ void __launch_bounds__(128, 3)
flash_mma_kernel()
{
    __shared__ float Ks[64][68];
    __shared__ float Vs[64][72];

    const int tid  = threadIdx.x;
    const int warp = tid >> 5;
    const int lane = tid & 31;
    const int grp  = lane >> 2;
    const int tg   = lane & 3;
    const int qb   = blockIdx.x;
    const int bh   = blockIdx.y;
    const int b    = bh >> 4;
    const int h    = bh & 15;
    const int q0   = qb * 64;
    const int m0   = warp * 16;

    const float* Qg = d_QKV;
    const float* Kg = d_QKV + (size_t)BS * Dn;
    const float* Vg = d_QKV + (size_t)2 * BS * Dn;

    // stage Q tile (scale by 1/8 — exact power of two, stays tf32)
#pragma unroll
    for (int i = 0; i < 8; i++) {
        int idx = tid + i * 128;
        int row = idx >> 4, c = (idx & 15) * 4;
        float4 v = *(const float4*)(Qg + (size_t)(b * Sn + q0 + row) * Dn + h * DH + c);
        *(float4*)&Ks[row][c] = make_float4(v.x * 0.125f, v.y * 0.125f,
                                            v.z * 0.125f, v.w * 0.125f);
    }
    __syncthreads();

    uint32_t qf[8][4];
#pragma unroll
    for (int dk = 0; dk < 8; dk++) {
        qf[dk][0] = __float_as_uint(Ks[m0 + grp][dk * 8 + tg]);
        qf[dk][1] = __float_as_uint(Ks[m0 + grp + 8][dk * 8 + tg]);
        qf[dk][2] = __float_as_uint(Ks[m0 + grp][dk * 8 + tg + 4]);
        qf[dk][3] = __float_as_uint(Ks[m0 + grp + 8][dk * 8 + tg + 4]);
    }
    __syncthreads();

    float co[8][4];
#pragma unroll
    for (int j = 0; j < 8; j++)
#pragma unroll
        for (int r = 0; r < 4; r++) co[j][r] = 0.f;
    float mr0 = -1e30f, mr1 = -1e30f, l0 = 0.f, l1 = 0.f;

    for (int kt = 0; kt <= qb; kt++) {
        const int k0 = kt * 64;

#pragma unroll
        for (int i = 0; i < 8; i++) {
            int idx = tid + i * 128;
            int row = idx >> 4, c = (idx & 15) * 4;
            size_t g = (size_t)(b * Sn + k0 + row) * Dn + h * DH + c;
            *(float4*)&Ks[row][c] = *(const float4*)(Kg + g);
            *(float4*)&Vs[row][c] = *(const float4*)(Vg + g);
        }
        __syncthreads();

        float cs[8][4];
#pragma unroll
        for (int j = 0; j < 8; j++) {
#pragma unroll
            for (int r = 0; r < 4; r++) cs[j][r] = 0.f;
#pragma unroll
            for (int dk = 0; dk < 8; dk++) {
                uint32_t b0 = __float_as_uint(Ks[j * 8 + grp][dk * 8 + tg]);
                uint32_t b1 = __float_as_uint(Ks[j * 8 + grp][dk * 8 + tg + 4]);
                mma_tf32(cs[j], qf[dk], b0, b1);
            }
        }

        if (kt == qb) {
            const int r0 = q0 + m0 + grp;
            const int r1 = r0 + 8;
#pragma unroll
            for (int j = 0; j < 8; j++) {
                const int ca = k0 + j * 8 + 2 * tg;
                if (ca > r0)     cs[j][0] = -1e30f;
                if (ca + 1 > r0) cs[j][1] = -1e30f;
                if (ca > r1)     cs[j][2] = -1e30f;
                if (ca + 1 > r1) cs[j][3] = -1e30f;
            }
        }

        float mx0 = mr0, mx1 = mr1;
#pragma unroll
        for (int j = 0; j < 8; j++) {
            mx0 = fmaxf(mx0, fmaxf(cs[j][0], cs[j][1]));
            mx1 = fmaxf(mx1, fmaxf(cs[j][2], cs[j][3]));
        }
        mx0 = fmaxf(mx0, __shfl_xor_sync(0xffffffffu, mx0, 1));
        mx0 = fmaxf(mx0, __shfl_xor_sync(0xffffffffu, mx0, 2));
        mx1 = fmaxf(mx1, __shfl_xor_sync(0xffffffffu, mx1, 1));
        mx1 = fmaxf(mx1, __shfl_xor_sync(0xffffffffu, mx1, 2));

        float corr0 = __expf(mr0 - mx0);
        float corr1 = __expf(mr1 - mx1);
        mr0 = mx0; mr1 = mx1;

        float s0 = 0.f, s1 = 0.f;
#pragma unroll
        for (int j = 0; j < 8; j++) {
            cs[j][0] = __expf(cs[j][0] - mx0); s0 += cs[j][0];
            cs[j][1] = __expf(cs[j][1] - mx0); s0 += cs[j][1];
            cs[j][2] = __expf(cs[j][2] - mx1); s1 += cs[j][2];
            cs[j][3] = __expf(cs[j][3] - mx1); s1 += cs[j][3];
        }
        s0 += __shfl_xor_sync(0xffffffffu, s0, 1);
        s0 += __shfl_xor_sync(0xffffffffu, s0, 2);
        s1 += __shfl_xor_sync(0xffffffffu, s1, 1);
        s1 += __shfl_xor_sync(0xffffffffu, s1, 2);
        l0 = l0 * corr0 + s0;
        l1 = l1 * corr1 + s1;

#pragma unroll
        for (int j = 0; j < 8; j++) {
            co[j][0] *= corr0; co[j][1] *= corr0;
            co[j][2] *= corr1; co[j][3] *= corr1;
        }

        const int base = lane & ~3;
        const int s1l = base + (tg >> 1);
        const int s2l = s1l + 2;
        const bool odd = tg & 1;
#pragma unroll
        for (int kk = 0; kk < 8; kk++) {
            float v00 = __shfl_sync(0xffffffffu, cs[kk][0], s1l);
            float v01 = __shfl_sync(0xffffffffu, cs[kk][1], s1l);
            float v02 = __shfl_sync(0xffffffffu, cs[kk][0], s2l);
            float v03 = __shfl_sync(0xffffffffu, cs[kk][1], s2l);
            float v10 = __shfl_sync(0xffffffffu, cs[kk][2], s1l);
            float v11 = __shfl_sync(0xffffffffu, cs[kk][3], s1l);
            float v12 = __shfl_sync(0xffffffffu, cs[kk][2], s2l);
            float v13 = __shfl_sync(0xffffffffu, cs[kk][3], s2l);
            uint32_t ap[4];
            ap[0] = __float_as_uint(to_tf32(odd ? v01 : v00));
            ap[1] = __float_as_uint(to_tf32(odd ? v11 : v10));
            ap[2] = __float_as_uint(to_tf32(odd ? v03 : v02));
            ap[3] = __float_as_uint(to_tf32(odd ? v13 : v12));
#pragma unroll
            for (int j = 0; j < 8; j++) {
                uint32_t b0 = __float_as_uint(Vs[kk * 8 + tg][j * 8 + grp]);
                uint32_t b1 = __float_as_uint(Vs[kk * 8 + tg + 4][j * 8 + grp]);
                mma_tf32(co[j], ap, b0, b1);
            }
        }
        __syncthreads();
    }

    const float i0 = 1.f / l0;
    const float i1 = 1.f / l1;
    const int r0 = q0 + m0 + grp;
    float* op0 = d_attn + (size_t)(b * Sn + r0) * Dn + h * DH;
    float* op1 = d_attn + (size_t)(b * Sn + r0 + 8) * Dn + h * DH;
#pragma unroll
    for (int j = 0; j < 8; j++) {
        const int cc = j * 8 + 2 * tg;
        *(float2*)(op0 + cc) = make_float2(to_tf32(co[j][0] * i0), to_tf32(co[j][1] * i0));
        *(float2*)(op1 + cc) = make_float2(to_tf32(co[j][2] * i1), to_tf32(co[j][3] * i1));
    }
}

// ---------------------------------------------------------------------------
// Host launch
// ---------------------------------------------------------------------------
extern "C" void kernel_launch(void* const* d_in, const int* in_sizes, int n_in,
                              void* d_out, int out_size)
{
    const float* x    = (const float*)d_in[0];
    const float* qk_f = (const float*)d_in[1];
    const float* qk_r = (const float*)d_in[2];
    const float* v_f  = (const float*)d_in[3];
    const float* v_r  = (const float*)d_in[4];
    const float* Wgq  = (const float*)d_in[5];
    const float* Wgk  = (const float*)d_in[6];
    const float* Wgv  = (const float*)d_in[7];
    const float* W_O  = (const float*)d_in[8];
    float* out = (float*)d_out;

    float *x32, *bfeat, *cf, *attn, *wo32;
    cudaGetSymbolAddress((void**)&x32,   d_x32);
    cudaGetSymbolAddress((void**)&bfeat, d_Bfeat);
    cudaGetSymbolAddress((void**)&cf,    d_CF);
    cudaGetSymbolAddress((void**)&attn,  d_attn);
    cudaGetSymbolAddress((void**)&wo32,  d_Wo32);

    static bool attrDone = false;
    if (!attrDone) {
        cudaFuncSetAttribute(gemm_ca, cudaFuncAttributeMaxDynamicSharedMemorySize, SMEM_BYTES);
        cudaFuncSetAttribute(gemm_restore_ca, cudaFuncAttributeMaxDynamicSharedMemorySize, SMEM_BYTES);
        attrDone = true;
    }

    dim3 t256(256);

    // 0) tf32-round all GEMM operands
    pack_misc<<<(X_ELEMS + 3 * R_ELEMS) / 1024, t256>>>(x, qk_r, v_r, W_O);
    pack_bfeat<<<Dn, t256>>>(Wgq, Wgk, Wgv, qk_f, v_f);

    // 1) Merged logits + features: [2048, 2816] = x32 @ Bfeat
    gemm_ca<<<dim3(NF / 128, BS / 128, 1), t256, SMEM_BYTES>>>(
        x32, bfeat, cf, Dn, NF, NF, 0);

    // 2) Softmax + group -> gates
    gate_kernel<<<dim3(BS, 3), t256>>>();

    // 3) Weighted mix -> hQ, hK, hV
    mix_kernel<<<BS, 128>>>();

    // 4) Aeff for Q,K,V (tf32)
    aeff3_kernel<<<BS, t256>>>();

    // 5) Restore: Q,K,V in one launch (z = 0..2), outputs tf32
    gemm_restore_ca<<<dim3(Dn / 128, BS / 128, 3), t256, SMEM_BYTES>>>();

    // 6) Tensor-core causal attention
    flash_mma_kernel<<<dim3(Sn / 64, Bn * NH), 128>>>();

    // 7) Output projection -> d_out
    gemm_ca<<<dim3(Dn / 128, BS / 128, 1), t256, SMEM_BYTES>>>(
        attn, wo32, out, Dn, Dn, Dn, 0);
}

// round 16
// speedup vs baseline: 1.7794x; 1.5586x over previous
#include <cuda_runtime.h>
#include <cuda_fp16.h>
#include <math.h>
#include <stdint.h>

// ---------------------------------------------------------------------------
// Problem constants
// ---------------------------------------------------------------------------
#define Bn  2
#define Sn  1024
#define Dn  1024
#define Mn  8
#define Rn  128
#define NNEUR 256
#define NH  16
#define DH  64
#define BS  (Bn * Sn)          // 2048 tokens
#define MR  (Mn * Rn)          // 1024
#define NF  2816               // merged feat width: 768 gate + 1024 qk + 1024 v
#define KP  512                // K in fp16-pairs (K=1024)

// GEMM smem geometry (3-stage cp.async pipeline) — uint32 (fp16x2) elements
#define A_STRIDE 20            // uint32 per A row (16 data + 4 pad)
#define B_STRIDE 136           // uint32 per B row (128 data + 8 pad)
#define A_STG (128 * A_STRIDE) // 2560 u32
#define B_STG (16 * B_STRIDE)  // 2176 u32
#define SMEM_BYTES (3 * (A_STG + B_STG) * 4)   // 56832

// ---------------------------------------------------------------------------
// Device scratch (allocation-free: __device__ globals)
// ---------------------------------------------------------------------------
__device__ uint32_t d_xh[BS * KP];             // x as fp16-pairs [2048][512]
__device__ uint32_t d_bfeath[KP * NF];         // [kp][col] packed B for feat
__device__ uint32_t d_brh[3 * KP * Dn];        // qk_r ; v_r ; W_O packed [kp][col]
__device__ float    d_CF[BS * NF];             // logits(768) + allh_qk + allh_v
__device__ uint32_t d_aeffh[3 * BS * KP];      // (g⊗h) fp16 pairs for Q,K,V
__device__ float    d_QKV[3 * BS * Dn];        // Q ; K ; V (tf32-rounded fp32)
__device__ uint32_t d_attnh[BS * KP];          // attention out, fp16 pairs

// ---------------------------------------------------------------------------
// Helpers
// ---------------------------------------------------------------------------
__device__ __forceinline__ float to_tf32(float x) {
    uint32_t u;
    asm("cvt.rna.tf32.f32 %0, %1;" : "=r"(u) : "f"(x));
    return __uint_as_float(u);
}

__device__ __forceinline__ uint32_t packh2(float a, float b) {
    __half2 h = __floats2half2_rn(a, b);
    return *(uint32_t*)&h;
}

// fp16 mma m16n8k16, fp32 accumulate
__device__ __forceinline__ void mma_f16(float c[4], const uint32_t a[4],
                                        uint32_t b0, uint32_t b1) {
    asm volatile(
        "mma.sync.aligned.m16n8k16.row.col.f32.f16.f16.f32 "
        "{%0,%1,%2,%3}, {%4,%5,%6,%7}, {%8,%9}, {%0,%1,%2,%3};\n"
        : "+f"(c[0]), "+f"(c[1]), "+f"(c[2]), "+f"(c[3])
        : "r"(a[0]), "r"(a[1]), "r"(a[2]), "r"(a[3]), "r"(b0), "r"(b1));
}

// tf32 mma (flash attention only)
__device__ __forceinline__ void mma_tf32(float c[4], const uint32_t a[4],
                                         uint32_t b0, uint32_t b1) {
    asm volatile(
        "mma.sync.aligned.m16n8k8.row.col.f32.tf32.tf32.f32 "
        "{%0,%1,%2,%3}, {%4,%5,%6,%7}, {%8,%9}, {%0,%1,%2,%3};\n"
        : "+f"(c[0]), "+f"(c[1]), "+f"(c[2]), "+f"(c[3])
        : "r"(a[0]), "r"(a[1]), "r"(a[2]), "r"(a[3]), "r"(b0), "r"(b1));
}

#define CPA(dst, src) \
    asm volatile("cp.async.cg.shared.global [%0], [%1], 16;\n" :: "r"(dst), "l"(src))
#define CPCOMMIT() asm volatile("cp.async.commit_group;\n")
#define CPWAIT2()  asm volatile("cp.async.wait_group 2;\n")

// ---------------------------------------------------------------------------
// FP16 GEMM body, K = 1024 fp16 = 512 pairs (32 k-tiles of 16 u32).
// BM=BN=128, 256 threads, 8 warps (warp tile 64x32), 3-stage cp.async.
// Identical structure/banks to the proven tf32 kernel; u32 = fp16x2 along k.
// lda/ldb in u32 units, ldc in floats.
// ---------------------------------------------------------------------------
__device__ __forceinline__ void
gemm_h_body(const uint32_t* __restrict__ A, const uint32_t* __restrict__ B,
            float* __restrict__ C, int lda, int ldb, int ldc, bool cvtOut)
{
    extern __shared__ uint32_t smu[];
    uint32_t* As = smu;                    // 3 stages [128][A_STRIDE]
    uint32_t* Bs = smu + 3 * A_STG;        // 3 stages [16][B_STRIDE]

    const int tid  = threadIdx.x;
    const int brow = blockIdx.y * 128;
    const int bcol = blockIdx.x * 128;

    const int warp = tid >> 5;
    const int lane = tid & 31;
    const int wm   = warp >> 2;
    const int wn   = warp & 3;
    const int grp  = lane >> 2;
    const int tg   = lane & 3;
    const int m0   = wm * 64;

    const int aRow = tid >> 2;               // 0..63
    const int aCol = (tid & 3) << 2;         // 0,4,8,12 (u32)
    const uint32_t* Asrc0 = A + (size_t)(brow + aRow) * lda + aCol;
    const uint32_t* Asrc1 = Asrc0 + (size_t)64 * lda;

    const int bRow = tid >> 5;               // 0..7
    const int bCol = (tid & 31) << 2;        // 0..124 (u32)
    const uint32_t* Bsrc0 = B + (size_t)bRow * ldb + bcol + bCol;
    const uint32_t* Bsrc1 = Bsrc0 + (size_t)8 * ldb;

    const uint32_t aBase = (uint32_t)__cvta_generic_to_shared(As);
    const uint32_t bBase = (uint32_t)__cvta_generic_to_shared(Bs);
    const uint32_t sA0 = aBase + (uint32_t)(aRow * A_STRIDE + aCol) * 4;
    const uint32_t sA1 = sA0 + 64 * A_STRIDE * 4;
    const uint32_t sB0 = bBase + (uint32_t)(bRow * B_STRIDE + bCol) * 4;
    const uint32_t sB1 = sB0 + 8 * B_STRIDE * 4;

#define ISSUE(s_, t_) do {                                        \
        const uint32_t oa = (uint32_t)(s_) * (A_STG * 4);          \
        const uint32_t ob = (uint32_t)(s_) * (B_STG * 4);          \
        CPA(sA0 + oa, Asrc0 + ((t_) << 4));                        \
        CPA(sA1 + oa, Asrc1 + ((t_) << 4));                        \
        CPA(sB0 + ob, Bsrc0 + (size_t)((t_) << 4) * ldb);          \
        CPA(sB1 + ob, Bsrc1 + (size_t)((t_) << 4) * ldb);          \
        CPCOMMIT(); } while (0)

    float c[4][4][4];
#pragma unroll
    for (int i = 0; i < 4; i++)
#pragma unroll
        for (int j = 0; j < 4; j++)
#pragma unroll
            for (int r = 0; r < 4; r++) c[i][j][r] = 0.f;

    ISSUE(0, 0);
    ISSUE(1, 1);
    ISSUE(2, 2);

    for (int t = 0; t < 32; t++) {
        const int s = t % 3;
        CPWAIT2();
        __syncthreads();

        const uint32_t* Ast = As + s * A_STG;
        const uint32_t* Bst = Bs + s * B_STG;

#pragma unroll
        for (int ks = 0; ks < 2; ks++) {
            const int kb = ks << 3;
            uint32_t af[4][4], bf[4][2];
#pragma unroll
            for (int i = 0; i < 4; i++) {
                const int r0 = (m0 + i * 16 + grp) * A_STRIDE;
                af[i][0] = Ast[r0 + kb + tg];
                af[i][1] = Ast[r0 + 8 * A_STRIDE + kb + tg];
                af[i][2] = Ast[r0 + kb + tg + 4];
                af[i][3] = Ast[r0 + 8 * A_STRIDE + kb + tg + 4];
            }
#pragma unroll
            for (int j = 0; j < 4; j++) {
                const int n0 = wn * 32 + j * 8 + grp;
                bf[j][0] = Bst[(kb + tg) * B_STRIDE + n0];
                bf[j][1] = Bst[(kb + tg + 4) * B_STRIDE + n0];
            }
#pragma unroll
            for (int i = 0; i < 4; i++)
#pragma unroll
                for (int j = 0; j < 4; j++)
                    mma_f16(c[i][j], af[i], bf[j][0], bf[j][1]);
        }

        __syncthreads();
        if (t + 3 < 32) ISSUE(s, t + 3); else CPCOMMIT();
    }
#undef ISSUE

#pragma unroll
    for (int i = 0; i < 4; i++) {
        const int r0 = brow + m0 + i * 16 + grp;
#pragma unroll
        for (int j = 0; j < 4; j++) {
            const int cc = bcol + wn * 32 + j * 8 + tg * 2;
            float v0 = c[i][j][0], v1 = c[i][j][1], v2 = c[i][j][2], v3 = c[i][j][3];
            if (cvtOut) {
                v0 = to_tf32(v0); v1 = to_tf32(v1);
                v2 = to_tf32(v2); v3 = to_tf32(v3);
            }
            *(float2*)&C[(size_t)r0 * ldc + cc]       = make_float2(v0, v1);
            *(float2*)&C[(size_t)(r0 + 8) * ldc + cc] = make_float2(v2, v3);
        }
    }
}

// -------- GEMM wrappers ----------------------------------------------------
__global__ void __launch_bounds__(256, 2)
gemm_h(const uint32_t* __restrict__ A, const uint32_t* __restrict__ B,
       float* __restrict__ C, int lda, int ldb, int ldc, int cvtOut)
{
    gemm_h_body(A, B, C, lda, ldb, ldc, cvtOut != 0);
}

// restore: z 0..2 -> Q (qk_r), K (qk_r), V (v_r); outputs tf32-rounded fp32
__global__ void __launch_bounds__(256, 2)
gemm_restore_h()
{
    const int z = blockIdx.z;
    const uint32_t* A = d_aeffh + (size_t)z * BS * KP;
    const uint32_t* B = d_brh + (size_t)(z < 2 ? 0 : 1) * KP * Dn;
    float* C = d_QKV + (size_t)z * BS * Dn;
    gemm_h_body(A, B, C, KP, Dn, Dn, true);
}

// ---------------------------------------------------------------------------
// pack_xh: x fp32 [2048][1024] -> fp16 pairs [2048][512]
// ---------------------------------------------------------------------------
__global__ void pack_xh(const float* __restrict__ x)
{
    const int i = blockIdx.x * 256 + threadIdx.x;     // u32 index
    const int row = i >> 9, kp = i & 511;
    float2 v = *(const float2*)(x + (size_t)row * Dn + 2 * kp);
    d_xh[i] = packh2(v.x, v.y);
}

// ---------------------------------------------------------------------------
// pack_brh: qk_r / v_r / W_O [1024][1024] -> [512][1024] fp16-pair rows
// grid (4, 512, 3), block 256
// ---------------------------------------------------------------------------
__global__ void pack_brh(const float* __restrict__ qk_r, const float* __restrict__ v_r,
                         const float* __restrict__ wo)
{
    const int col = blockIdx.x * 256 + threadIdx.x;
    const int kp  = blockIdx.y;
    const int z   = blockIdx.z;
    const float* s = (z == 0) ? qk_r : (z == 1) ? v_r : wo;
    float a = s[(size_t)(2 * kp) * Dn + col];
    float b = s[(size_t)(2 * kp + 1) * Dn + col];
    d_brh[(size_t)z * KP * Dn + (size_t)kp * Dn + col] = packh2(a, b);
}

// ---------------------------------------------------------------------------
// pack_bfeath: build [512][2816] fp16-pair rows of [Wg_q|Wg_k|Wg_v|qk_f|v_f]
// grid (11, 512), block 256
// ---------------------------------------------------------------------------
__device__ __forceinline__ float feat_elem(
    const float* wq, const float* wk, const float* wv,
    const float* qkf, const float* vf, int d, int col)
{
    if (col < 768) {
        const int which = col >> 8;
        const int n = col & 255;
        const float* w = (which == 0) ? wq : (which == 1) ? wk : wv;
        return w[(size_t)d * NNEUR + n];
    } else if (col < 1792) {
        const int cc = col - 768;
        return qkf[((size_t)(cc >> 7) * Dn + d) * Rn + (cc & 127)];
    } else {
        const int cc = col - 1792;
        return vf[((size_t)(cc >> 7) * Dn + d) * Rn + (cc & 127)];
    }
}

__global__ void pack_bfeath(const float* __restrict__ wq, const float* __restrict__ wk,
                            const float* __restrict__ wv, const float* __restrict__ qkf,
                            const float* __restrict__ vf)
{
    const int col = blockIdx.x * 256 + threadIdx.x;
    const int kp  = blockIdx.y;
    float a = feat_elem(wq, wk, wv, qkf, vf, 2 * kp, col);
    float b = feat_elem(wq, wk, wv, qkf, vf, 2 * kp + 1, col);
    d_bfeath[(size_t)kp * NF + col] = packh2(a, b);
}

// ---------------------------------------------------------------------------
// Fused gate softmax + grouping + mix + aeff. grid = BS, block = 256.
// Reads logits + features from d_CF row; writes fp16-pair aeff for Q,K,V.
// ---------------------------------------------------------------------------
__global__ void gma_kernel()
{
    const int token = blockIdx.x;
    const int t = threadIdx.x;
    const float* row = d_CF + (size_t)token * NF;

    __shared__ float red[256];
    __shared__ float gs[3][8];
    __shared__ float gn[3][8];
    __shared__ float hsm[3][128];

    // three 256-way softmaxes, grouped by warp (32 consecutive neurons)
#pragma unroll
    for (int which = 0; which < 3; which++) {
        float v = row[which * NNEUR + t];
        red[t] = v; __syncthreads();
#pragma unroll
        for (int s = 128; s > 0; s >>= 1) {
            if (t < s) red[t] = fmaxf(red[t], red[t + s]);
            __syncthreads();
        }
        float mx = red[0];
        __syncthreads();
        float e = __expf(v - mx);
#pragma unroll
        for (int off = 16; off; off >>= 1)
            e += __shfl_down_sync(0xffffffffu, e, off);
        if ((t & 31) == 0) gs[which][t >> 5] = e;
        __syncthreads();
    }

    if (t < 24) {
        const int w = t >> 3, m = t & 7;
        float tot = 0.f;
#pragma unroll
        for (int i = 0; i < 8; i++) tot += gs[w][i];
        gn[w][m] = gs[w][m] / (tot * (1.0f + 1e-8f));
    }
    __syncthreads();

    // mix: h_z[r] = sum_m gn[z][m] * allh[m][r]
    if (t < 128) {
        float hq = 0.f, hk = 0.f;
#pragma unroll
        for (int m = 0; m < Mn; m++) {
            float a = row[768 + m * Rn + t];
            hq = fmaf(gn[0][m], a, hq);
            hk = fmaf(gn[1][m], a, hk);
        }
        hsm[0][t] = hq;
        hsm[1][t] = hk;
    } else {
        const int r = t - 128;
        float hv = 0.f;
#pragma unroll
        for (int m = 0; m < Mn; m++)
            hv = fmaf(gn[2][m], row[1792 + m * Rn + r], hv);
        hsm[2][r] = hv;
    }
    __syncthreads();

    // aeff: k = m*128 + r ; thread handles 4 consecutive k = 2 u32 per z
    const int cidx = t * 4;
    const int m = cidx >> 7;
    const int r = cidx & 127;
#pragma unroll
    for (int z = 0; z < 3; z++) {
        const float g = gn[z][m];
        float h0 = hsm[z][r], h1 = hsm[z][r + 1];
        float h2 = hsm[z][r + 2], h3 = hsm[z][r + 3];
        uint32_t* dst = d_aeffh + (size_t)z * BS * KP + (size_t)token * KP + t * 2;
        dst[0] = packh2(g * h0, g * h1);
        dst[1] = packh2(g * h2, g * h3);
    }
}

// ---------------------------------------------------------------------------
// Tensor-core causal flash attention (TF32 m16n8k8). Q/K/V tf32-rounded fp32.
// Block 128 threads (4 warps), 64 query rows. Grid (S/64, B*NH).
// Epilogue writes fp16-pair rows into d_attnh for the W_O GEMM.
// ---------------------------------------------------------------------------
__global__ void __launch_bounds__(128, 3)
flash_mma_kernel()
{
    __shared__ float Ks[64][68];
    __shared__ float Vs[64][72];

    const int tid  = threadIdx.x;
    const int warp = tid >> 5;
    const int lane = tid & 31;
    const int grp  = lane >> 2;
    const int tg   = lane & 3;
    const int qb   = blockIdx.x;
    const int bh   = blockIdx.y;
    const int b    = bh >> 4;
    const int h    = bh & 15;
    const int q0   = qb * 64;
    const int m0   = warp * 16;

    const float* Qg = d_QKV;
    const float* Kg = d_QKV + (size_t)BS * Dn;
    const float* Vg = d_QKV + (size_t)2 * BS * Dn;

#pragma unroll
    for (int i = 0; i < 8; i++) {
        int idx = tid + i * 128;
        int row = idx >> 4, c = (idx & 15) * 4;
        float4 v = *(const float4*)(Qg + (size_t)(b * Sn + q0 + row) * Dn + h * DH + c);
        *(float4*)&Ks[row][c] = make_float4(v.x * 0.125f, v.y * 0.125f,
                                            v.z * 0.125f, v.w * 0.125f);
    }
    __syncthreads();

    uint32_t qf[8][4];
#pragma unroll
    for (int dk = 0; dk < 8; dk++) {
        qf[dk][0] = __float_as_uint(Ks[m0 + grp][dk * 8 + tg]);
        qf[dk][1] = __float_as_uint(Ks[m0 + grp + 8][dk * 8 + tg]);
        qf[dk][2] = __float_as_uint(Ks[m0 + grp][dk * 8 + tg + 4]);
        qf[dk][3] = __float_as_uint(Ks[m0 + grp + 8][dk * 8 + tg + 4]);
    }
    __syncthreads();

    float co[8][4];
#pragma unroll
    for (int j = 0; j < 8; j++)
#pragma unroll
        for (int r = 0; r < 4; r++) co[j][r] = 0.f;
    float mr0 = -1e30f, mr1 = -1e30f, l0 = 0.f, l1 = 0.f;

    for (int kt = 0; kt <= qb; kt++) {
        const int k0 = kt * 64;

#pragma unroll
        for (int i = 0; i < 8; i++) {
            int idx = tid + i * 128;
            int row = idx >> 4, c = (idx & 15) * 4;
            size_t g = (size_t)(b * Sn + k0 + row) * Dn + h * DH + c;
            *(float4*)&Ks[row][c] = *(const float4*)(Kg + g);
            *(float4*)&Vs[row][c] = *(const float4*)(Vg + g);
        }
        __syncthreads();

        float cs[8][4];
#pragma unroll
        for (int j = 0; j < 8; j++) {
#pragma unroll
            for (int r = 0; r < 4; r++) cs[j][r] = 0.f;
#pragma unroll
            for (int dk = 0; dk < 8; dk++) {
                uint32_t b0 = __float_as_uint(Ks[j * 8 + grp][dk * 8 + tg]);
                uint32_t b1 = __float_as_uint(Ks[j * 8 + grp][dk * 8 + tg + 4]);
                mma_tf32(cs[j], qf[dk], b0, b1);
            }
        }

        if (kt == qb) {
            const int r0 = q0 + m0 + grp;
            const int r1 = r0 + 8;
#pragma unroll
            for (int j = 0; j < 8; j++) {
                const int ca = k0 + j * 8 + 2 * tg;
                if (ca > r0)     cs[j][0] = -1e30f;
                if (ca + 1 > r0) cs[j][1] = -1e30f;
                if (ca > r1)     cs[j][2] = -1e30f;
                if (ca + 1 > r1) cs[j][3] = -1e30f;
            }
        }

        float mx0 = mr0, mx1 = mr1;
#pragma unroll
        for (int j = 0; j < 8; j++) {
            mx0 = fmaxf(mx0, fmaxf(cs[j][0], cs[j][1]));
            mx1 = fmaxf(mx1, fmaxf(cs[j][2], cs[j][3]));
        }
        mx0 = fmaxf(mx0, __shfl_xor_sync(0xffffffffu, mx0, 1));
        mx0 = fmaxf(mx0, __shfl_xor_sync(0xffffffffu, mx0, 2));
        mx1 = fmaxf(mx1, __shfl_xor_sync(0xffffffffu, mx1, 1));
        mx1 = fmaxf(mx1, __shfl_xor_sync(0xffffffffu, mx1, 2));

        float corr0 = __expf(mr0 - mx0);
        float corr1 = __expf(mr1 - mx1);
        mr0 = mx0; mr1 = mx1;

        float s0 = 0.f, s1 = 0.f;
#pragma unroll
        for (int j = 0; j < 8; j++) {
            cs[j][0] = __expf(cs[j][0] - mx0); s0 += cs[j][0];
            cs[j][1] = __expf(cs[j][1] - mx0); s0 += cs[j][1];
            cs[j][2] = __expf(cs[j][2] - mx1); s1 += cs[j][2];
            cs[j][3] = __expf(cs[j][3] - mx1); s1 += cs[j][3];
        }
        s0 += __shfl_xor_sync(0xffffffffu, s0, 1);
        s0 += __shfl_xor_sync(0xffffffffu, s0, 2);
        s1 += __shfl_xor_sync(0xffffffffu, s1, 1);
        s1 += __shfl_xor_sync(0xffffffffu, s1, 2);
        l0 = l0 * corr0 + s0;
        l1 = l1 * corr1 + s1;

#pragma unroll
        for (int j = 0; j < 8; j++) {
            co[j][0] *= corr0; co[j][1] *= corr0;
            co[j][2] *= corr1; co[j][3] *= corr1;
        }

        const int base = lane & ~3;
        const int s1l = base + (tg >> 1);
        const int s2l = s1l + 2;
        const bool odd = tg & 1;
#pragma unroll
        for (int kk = 0; kk < 8; kk++) {
            float v00 = __shfl_sync(0xffffffffu, cs[kk][0], s1l);
            float v01 = __shfl_sync(0xffffffffu, cs[kk][1], s1l);
            float v02 = __shfl_sync(0xffffffffu, cs[kk][0], s2l);
            float v03 = __shfl_sync(0xffffffffu, cs[kk][1], s2l);
            float v10 = __shfl_sync(0xffffffffu, cs[kk][2], s1l);
            float v11 = __shfl_sync(0xffffffffu, cs[kk][3], s1l);
            float v12 = __shfl_sync(0xffffffffu, cs[kk][2], s2l);
            float v13 = __shfl_sync(0xffffffffu, cs[kk][3], s2l);
            uint32_t ap[4];
            ap[0] = __float_as_uint(to_tf32(odd ? v01 : v00));
            ap[1] = __float_as_uint(to_tf32(odd ? v11 : v10));
            ap[2] = __float_as_uint(to_tf32(odd ? v03 : v02));
            ap[3] = __float_as_uint(to_tf32(odd ? v13 : v12));
#pragma unroll
            for (int j = 0; j < 8; j++) {
                uint32_t b0 = __float_as_uint(Vs[kk * 8 + tg][j * 8 + grp]);
                uint32_t b1 = __float_as_uint(Vs[kk * 8 + tg + 4][j * 8 + grp]);
                mma_tf32(co[j], ap, b0, b1);
            }
        }
        __syncthreads();
    }

    // epilogue: write fp16 pairs (consecutive head-dim columns) for W_O GEMM
    const float i0 = 1.f / l0;
    const float i1 = 1.f / l1;
    const int r0 = q0 + m0 + grp;
    uint32_t* op0 = d_attnh + (size_t)(b * Sn + r0) * KP + (h * DH) / 2;
    uint32_t* op1 = d_attnh + (size_t)(b * Sn + r0 + 8) * KP + (h * DH) / 2;
#pragma unroll
    for (int j = 0; j < 8; j++) {
        const int p = j * 4 + tg;                     // pair index within head
        op0[p] = packh2(co[j][0] * i0, co[j][1] * i0);
        op1[p] = packh2(co[j][2] * i1, co[j][3] * i1);
    }
}

// ---------------------------------------------------------------------------
// Host launch
// ---------------------------------------------------------------------------
extern "C" void kernel_launch(void* const* d_in, const int* in_sizes, int n_in,
                              void* d_out, int out_size)
{
    const float* x    = (const float*)d_in[0];
    const float* qk_f = (const float*)d_in[1];
    const float* qk_r = (const float*)d_in[2];
    const float* v_f  = (const float*)d_in[3];
    const float* v_r  = (const float*)d_in[4];
    const float* Wgq  = (const float*)d_in[5];
    const float* Wgk  = (const float*)d_in[6];
    const float* Wgv  = (const float*)d_in[7];
    const float* W_O  = (const float*)d_in[8];
    float* out = (float*)d_out;

    uint32_t *xh, *bfeath, *brh, *attnh;
    float *cf;
    cudaGetSymbolAddress((void**)&xh,     d_xh);
    cudaGetSymbolAddress((void**)&bfeath, d_bfeath);
    cudaGetSymbolAddress((void**)&brh,    d_brh);
    cudaGetSymbolAddress((void**)&cf,     d_CF);
    cudaGetSymbolAddress((void**)&attnh,  d_attnh);

    static bool attrDone = false;
    if (!attrDone) {
        cudaFuncSetAttribute(gemm_h, cudaFuncAttributeMaxDynamicSharedMemorySize, SMEM_BYTES);
        cudaFuncSetAttribute(gemm_restore_h, cudaFuncAttributeMaxDynamicSharedMemorySize, SMEM_BYTES);
        attrDone = true;
    }

    dim3 t256(256);

    // 0) pack operands to fp16 pairs
    pack_xh<<<(BS * KP) / 256, t256>>>(x);
    pack_brh<<<dim3(4, KP, 3), t256>>>(qk_r, v_r, W_O);
    pack_bfeath<<<dim3(NF / 256, KP), t256>>>(Wgq, Wgk, Wgv, qk_f, v_f);

    // 1) Merged logits + features: [2048, 2816] = xh @ bfeath
    gemm_h<<<dim3(NF / 128, BS / 128, 1), t256, SMEM_BYTES>>>(
        xh, bfeath, cf, KP, NF, NF, 0);

    // 2) Fused gates + mix + aeff (fp16 pairs)
    gma_kernel<<<BS, t256>>>();

    // 3) Restore: Q,K,V in one launch (z = 0..2), outputs tf32-rounded fp32
    gemm_restore_h<<<dim3(Dn / 128, BS / 128, 3), t256, SMEM_BYTES>>>();

    // 4) Tensor-core causal attention (tf32), epilogue packs fp16 pairs
    flash_mma_kernel<<<dim3(Sn / 64, Bn * NH), 128>>>();

    // 5) Output projection -> d_out
    gemm_h<<<dim3(Dn / 128, BS / 128, 1), t256, SMEM_BYTES>>>(
        attnh, brh + (size_t)2 * KP * Dn, out, KP, Dn, Dn, 0);
}

// round 17
// speedup vs baseline: 1.8563x; 1.0432x over previous
#include <cuda_runtime.h>
#include <cuda_fp16.h>
#include <math.h>
#include <stdint.h>

// ---------------------------------------------------------------------------
// Problem constants
// ---------------------------------------------------------------------------
#define Bn  2
#define Sn  1024
#define Dn  1024
#define Mn  8
#define Rn  128
#define NNEUR 256
#define NH  16
#define DH  64
#define BS  (Bn * Sn)          // 2048 tokens
#define MR  (Mn * Rn)          // 1024
#define NF  2816               // merged feat width: 768 gate + 1024 qk + 1024 v
#define KP  512                // K in fp16-pairs (K=1024)

// GEMM smem geometry (3-stage cp.async pipeline) — uint32 (fp16x2) elements
#define A_STRIDE 20            // uint32 per A row (16 data + 4 pad)
#define B_STRIDE 136           // uint32 per B row (128 data + 8 pad)
#define A_STG (128 * A_STRIDE) // 2560 u32
#define B_STG (16 * B_STRIDE)  // 2176 u32
#define SMEM_BYTES (3 * (A_STG + B_STG) * 4)   // 56832

// ---------------------------------------------------------------------------
// Device scratch (allocation-free: __device__ globals)
// ---------------------------------------------------------------------------
__device__ uint32_t d_xh[BS * KP];             // x as fp16-pairs [2048][512]
__device__ uint32_t d_bfeath[KP * NF];         // [kp][col] packed B for feat
__device__ uint32_t d_brh[3 * KP * Dn];        // qk_r ; v_r ; W_O packed [kp][col]
__device__ float    d_CF[BS * NF];             // logits(768) + allh_qk + allh_v
__device__ uint32_t d_aeffh[3 * BS * KP];      // (g⊗h) fp16 pairs for Q,K,V
__device__ uint32_t d_QKVh[3 * BS * KP];       // Q(pre-scaled) ; K ; V fp16 pairs
__device__ uint32_t d_attnh[BS * KP];          // attention out, fp16 pairs

// ---------------------------------------------------------------------------
// Helpers
// ---------------------------------------------------------------------------
__device__ __forceinline__ uint32_t packh2(float a, float b) {
    __half2 h = __floats2half2_rn(a, b);
    return *(uint32_t*)&h;
}

// fp16 mma m16n8k16, fp32 accumulate
__device__ __forceinline__ void mma_f16(float c[4], const uint32_t a[4],
                                        uint32_t b0, uint32_t b1) {
    asm volatile(
        "mma.sync.aligned.m16n8k16.row.col.f32.f16.f16.f32 "
        "{%0,%1,%2,%3}, {%4,%5,%6,%7}, {%8,%9}, {%0,%1,%2,%3};\n"
        : "+f"(c[0]), "+f"(c[1]), "+f"(c[2]), "+f"(c[3])
        : "r"(a[0]), "r"(a[1]), "r"(a[2]), "r"(a[3]), "r"(b0), "r"(b1));
}

#define CPA(dst, src) \
    asm volatile("cp.async.cg.shared.global [%0], [%1], 16;\n" :: "r"(dst), "l"(src))
#define CPCOMMIT() asm volatile("cp.async.commit_group;\n")
#define CPWAIT2()  asm volatile("cp.async.wait_group 2;\n")

// ---------------------------------------------------------------------------
// FP16 GEMM body, K = 1024 fp16 = 512 pairs (32 k-tiles of 16 u32).
// BM=BN=128, 256 threads, 8 warps (warp tile 64x32), 3-stage cp.async.
// outHalf=false: write fp32 to Cf (ldc floats).
// outHalf=true : write packed fp16 pairs * oscale to Ch (ldc u32 pairs).
// ---------------------------------------------------------------------------
__device__ __forceinline__ void
gemm_h_body(const uint32_t* __restrict__ A, const uint32_t* __restrict__ B,
            float* __restrict__ Cf, uint32_t* __restrict__ Ch,
            int lda, int ldb, int ldc, float oscale, bool outHalf)
{
    extern __shared__ uint32_t smu[];
    uint32_t* As = smu;                    // 3 stages [128][A_STRIDE]
    uint32_t* Bs = smu + 3 * A_STG;        // 3 stages [16][B_STRIDE]

    const int tid  = threadIdx.x;
    const int brow = blockIdx.y * 128;
    const int bcol = blockIdx.x * 128;

    const int warp = tid >> 5;
    const int lane = tid & 31;
    const int wm   = warp >> 2;
    const int wn   = warp & 3;
    const int grp  = lane >> 2;
    const int tg   = lane & 3;
    const int m0   = wm * 64;

    const int aRow = tid >> 2;               // 0..63
    const int aCol = (tid & 3) << 2;         // 0,4,8,12 (u32)
    const uint32_t* Asrc0 = A + (size_t)(brow + aRow) * lda + aCol;
    const uint32_t* Asrc1 = Asrc0 + (size_t)64 * lda;

    const int bRow = tid >> 5;               // 0..7
    const int bCol = (tid & 31) << 2;        // 0..124 (u32)
    const uint32_t* Bsrc0 = B + (size_t)bRow * ldb + bcol + bCol;
    const uint32_t* Bsrc1 = Bsrc0 + (size_t)8 * ldb;

    const uint32_t aBase = (uint32_t)__cvta_generic_to_shared(As);
    const uint32_t bBase = (uint32_t)__cvta_generic_to_shared(Bs);
    const uint32_t sA0 = aBase + (uint32_t)(aRow * A_STRIDE + aCol) * 4;
    const uint32_t sA1 = sA0 + 64 * A_STRIDE * 4;
    const uint32_t sB0 = bBase + (uint32_t)(bRow * B_STRIDE + bCol) * 4;
    const uint32_t sB1 = sB0 + 8 * B_STRIDE * 4;

#define ISSUE(s_, t_) do {                                        \
        const uint32_t oa = (uint32_t)(s_) * (A_STG * 4);          \
        const uint32_t ob = (uint32_t)(s_) * (B_STG * 4);          \
        CPA(sA0 + oa, Asrc0 + ((t_) << 4));                        \
        CPA(sA1 + oa, Asrc1 + ((t_) << 4));                        \
        CPA(sB0 + ob, Bsrc0 + (size_t)((t_) << 4) * ldb);          \
        CPA(sB1 + ob, Bsrc1 + (size_t)((t_) << 4) * ldb);          \
        CPCOMMIT(); } while (0)

    float c[4][4][4];
#pragma unroll
    for (int i = 0; i < 4; i++)
#pragma unroll
        for (int j = 0; j < 4; j++)
#pragma unroll
            for (int r = 0; r < 4; r++) c[i][j][r] = 0.f;

    ISSUE(0, 0);
    ISSUE(1, 1);
    ISSUE(2, 2);

    for (int t = 0; t < 32; t++) {
        const int s = t % 3;
        CPWAIT2();
        __syncthreads();

        const uint32_t* Ast = As + s * A_STG;
        const uint32_t* Bst = Bs + s * B_STG;

#pragma unroll
        for (int ks = 0; ks < 2; ks++) {
            const int kb = ks << 3;
            uint32_t af[4][4], bf[4][2];
#pragma unroll
            for (int i = 0; i < 4; i++) {
                const int r0 = (m0 + i * 16 + grp) * A_STRIDE;
                af[i][0] = Ast[r0 + kb + tg];
                af[i][1] = Ast[r0 + 8 * A_STRIDE + kb + tg];
                af[i][2] = Ast[r0 + kb + tg + 4];
                af[i][3] = Ast[r0 + 8 * A_STRIDE + kb + tg + 4];
            }
#pragma unroll
            for (int j = 0; j < 4; j++) {
                const int n0 = wn * 32 + j * 8 + grp;
                bf[j][0] = Bst[(kb + tg) * B_STRIDE + n0];
                bf[j][1] = Bst[(kb + tg + 4) * B_STRIDE + n0];
            }
#pragma unroll
            for (int i = 0; i < 4; i++)
#pragma unroll
                for (int j = 0; j < 4; j++)
                    mma_f16(c[i][j], af[i], bf[j][0], bf[j][1]);
        }

        __syncthreads();
        if (t + 3 < 32) ISSUE(s, t + 3); else CPCOMMIT();
    }
#undef ISSUE

#pragma unroll
    for (int i = 0; i < 4; i++) {
        const int r0 = brow + m0 + i * 16 + grp;
#pragma unroll
        for (int j = 0; j < 4; j++) {
            const int cc = bcol + wn * 32 + j * 8 + tg * 2;
            if (!outHalf) {
                *(float2*)&Cf[(size_t)r0 * ldc + cc] =
                    make_float2(c[i][j][0], c[i][j][1]);
                *(float2*)&Cf[(size_t)(r0 + 8) * ldc + cc] =
                    make_float2(c[i][j][2], c[i][j][3]);
            } else {
                Ch[(size_t)r0 * ldc + (cc >> 1)] =
                    packh2(c[i][j][0] * oscale, c[i][j][1] * oscale);
                Ch[(size_t)(r0 + 8) * ldc + (cc >> 1)] =
                    packh2(c[i][j][2] * oscale, c[i][j][3] * oscale);
            }
        }
    }
}

// -------- GEMM wrappers ----------------------------------------------------
__global__ void __launch_bounds__(256, 2)
gemm_h(const uint32_t* __restrict__ A, const uint32_t* __restrict__ B,
       float* __restrict__ C, int lda, int ldb, int ldc)
{
    gemm_h_body(A, B, C, nullptr, lda, ldb, ldc, 1.f, false);
}

// restore: z 0..2 -> Q (qk_r, pre-scaled 1/8), K (qk_r), V (v_r); fp16 out
__global__ void __launch_bounds__(256, 2)
gemm_restore_h()
{
    const int z = blockIdx.z;
    const uint32_t* A = d_aeffh + (size_t)z * BS * KP;
    const uint32_t* B = d_brh + (size_t)(z < 2 ? 0 : 1) * KP * Dn;
    uint32_t* Ch = d_QKVh + (size_t)z * BS * KP;
    gemm_h_body(A, B, nullptr, Ch, KP, Dn, KP, (z == 0) ? 0.125f : 1.0f, true);
}

// ---------------------------------------------------------------------------
// pack_xh: x fp32 [2048][1024] -> fp16 pairs [2048][512]
// ---------------------------------------------------------------------------
__global__ void pack_xh(const float* __restrict__ x)
{
    const int i = blockIdx.x * 256 + threadIdx.x;     // u32 index
    const int row = i >> 9, kp = i & 511;
    float2 v = *(const float2*)(x + (size_t)row * Dn + 2 * kp);
    d_xh[i] = packh2(v.x, v.y);
}

// ---------------------------------------------------------------------------
// pack_brh: qk_r / v_r / W_O [1024][1024] -> [512][1024] fp16-pair rows
// ---------------------------------------------------------------------------
__global__ void pack_brh(const float* __restrict__ qk_r, const float* __restrict__ v_r,
                         const float* __restrict__ wo)
{
    const int col = blockIdx.x * 256 + threadIdx.x;
    const int kp  = blockIdx.y;
    const int z   = blockIdx.z;
    const float* s = (z == 0) ? qk_r : (z == 1) ? v_r : wo;
    float a = s[(size_t)(2 * kp) * Dn + col];
    float b = s[(size_t)(2 * kp + 1) * Dn + col];
    d_brh[(size_t)z * KP * Dn + (size_t)kp * Dn + col] = packh2(a, b);
}

// ---------------------------------------------------------------------------
// pack_bfeath: build [512][2816] fp16-pair rows of [Wg_q|Wg_k|Wg_v|qk_f|v_f]
// ---------------------------------------------------------------------------
__device__ __forceinline__ float feat_elem(
    const float* wq, const float* wk, const float* wv,
    const float* qkf, const float* vf, int d, int col)
{
    if (col < 768) {
        const int which = col >> 8;
        const int n = col & 255;
        const float* w = (which == 0) ? wq : (which == 1) ? wk : wv;
        return w[(size_t)d * NNEUR + n];
    } else if (col < 1792) {
        const int cc = col - 768;
        return qkf[((size_t)(cc >> 7) * Dn + d) * Rn + (cc & 127)];
    } else {
        const int cc = col - 1792;
        return vf[((size_t)(cc >> 7) * Dn + d) * Rn + (cc & 127)];
    }
}

__global__ void pack_bfeath(const float* __restrict__ wq, const float* __restrict__ wk,
                            const float* __restrict__ wv, const float* __restrict__ qkf,
                            const float* __restrict__ vf)
{
    const int col = blockIdx.x * 256 + threadIdx.x;
    const int kp  = blockIdx.y;
    float a = feat_elem(wq, wk, wv, qkf, vf, 2 * kp, col);
    float b = feat_elem(wq, wk, wv, qkf, vf, 2 * kp + 1, col);
    d_bfeath[(size_t)kp * NF + col] = packh2(a, b);
}

// ---------------------------------------------------------------------------
// Fused gate softmax + grouping + mix + aeff. grid = BS, block = 256.
// ---------------------------------------------------------------------------
__global__ void gma_kernel()
{
    const int token = blockIdx.x;
    const int t = threadIdx.x;
    const float* row = d_CF + (size_t)token * NF;

    __shared__ float red[256];
    __shared__ float gs[3][8];
    __shared__ float gn[3][8];
    __shared__ float hsm[3][128];

#pragma unroll
    for (int which = 0; which < 3; which++) {
        float v = row[which * NNEUR + t];
        red[t] = v; __syncthreads();
#pragma unroll
        for (int s = 128; s > 0; s >>= 1) {
            if (t < s) red[t] = fmaxf(red[t], red[t + s]);
            __syncthreads();
        }
        float mx = red[0];
        __syncthreads();
        float e = __expf(v - mx);
#pragma unroll
        for (int off = 16; off; off >>= 1)
            e += __shfl_down_sync(0xffffffffu, e, off);
        if ((t & 31) == 0) gs[which][t >> 5] = e;
        __syncthreads();
    }

    if (t < 24) {
        const int w = t >> 3, m = t & 7;
        float tot = 0.f;
#pragma unroll
        for (int i = 0; i < 8; i++) tot += gs[w][i];
        gn[w][m] = gs[w][m] / (tot * (1.0f + 1e-8f));
    }
    __syncthreads();

    if (t < 128) {
        float hq = 0.f, hk = 0.f;
#pragma unroll
        for (int m = 0; m < Mn; m++) {
            float a = row[768 + m * Rn + t];
            hq = fmaf(gn[0][m], a, hq);
            hk = fmaf(gn[1][m], a, hk);
        }
        hsm[0][t] = hq;
        hsm[1][t] = hk;
    } else {
        const int r = t - 128;
        float hv = 0.f;
#pragma unroll
        for (int m = 0; m < Mn; m++)
            hv = fmaf(gn[2][m], row[1792 + m * Rn + r], hv);
        hsm[2][r] = hv;
    }
    __syncthreads();

    const int cidx = t * 4;
    const int m = cidx >> 7;
    const int r = cidx & 127;
#pragma unroll
    for (int z = 0; z < 3; z++) {
        const float g = gn[z][m];
        float h0 = hsm[z][r], h1 = hsm[z][r + 1];
        float h2 = hsm[z][r + 2], h3 = hsm[z][r + 3];
        uint32_t* dst = d_aeffh + (size_t)z * BS * KP + (size_t)token * KP + t * 2;
        dst[0] = packh2(g * h0, g * h1);
        dst[1] = packh2(g * h2, g * h3);
    }
}

// ---------------------------------------------------------------------------
// FP16 tensor-core causal flash attention (m16n8k16, fp32 accumulate).
// Block 128 threads (4 warps), 64 query rows. Grid (S/64, B*NH).
// Q pre-scaled by 1/8 in restore epilogue. K smem [key][pair] stride 36;
// V smem transposed [dh][key-pair] stride 36 — all fragment LDS conflict-free
// (bank = 4*grp + tg, 32 distinct). P A-frags come straight from the S
// accumulator (no shuffles).
// ---------------------------------------------------------------------------
__global__ void __launch_bounds__(128, 4)
flash_h_kernel()
{
    __shared__ uint32_t Ks[64][36];   // Q staging, then K tiles
    __shared__ uint32_t Vt[64][36];   // V transposed: [dh][key-pair]

    const int tid  = threadIdx.x;
    const int warp = tid >> 5;
    const int lane = tid & 31;
    const int grp  = lane >> 2;
    const int tg   = lane & 3;
    const int qb   = blockIdx.x;
    const int bh   = blockIdx.y;
    const int b    = bh >> 4;
    const int h    = bh & 15;
    const int q0   = qb * 64;
    const int m0   = warp * 16;

    const uint32_t* Qh = d_QKVh;
    const uint32_t* Kh = d_QKVh + (size_t)BS * KP;
    const uint32_t* Vh = d_QKVh + (size_t)2 * BS * KP;

    // ---- stage Q tile (coalesced), build fp16 A-fragments ----
#pragma unroll
    for (int i = 0; i < 4; i++) {
        int idx = tid + i * 128;
        int row = idx >> 3, c4 = (idx & 7) * 4;
        uint4 v = *(const uint4*)(Qh + (size_t)(b * Sn + q0 + row) * KP + h * 32 + c4);
        *(uint4*)&Ks[row][c4] = v;
    }
    __syncthreads();

    uint32_t qf[4][4];
#pragma unroll
    for (int ks = 0; ks < 4; ks++) {
        qf[ks][0] = Ks[m0 + grp][8 * ks + tg];
        qf[ks][1] = Ks[m0 + grp + 8][8 * ks + tg];
        qf[ks][2] = Ks[m0 + grp][8 * ks + tg + 4];
        qf[ks][3] = Ks[m0 + grp + 8][8 * ks + tg + 4];
    }
    __syncthreads();

    float co[8][4];
#pragma unroll
    for (int j = 0; j < 8; j++)
#pragma unroll
        for (int r = 0; r < 4; r++) co[j][r] = 0.f;
    float mr0 = -1e30f, mr1 = -1e30f, l0 = 0.f, l1 = 0.f;

    for (int kt = 0; kt <= qb; kt++) {
        const int k0 = kt * 64;

        // K tile: coalesced uint4 loads, [key][pair]
#pragma unroll
        for (int i = 0; i < 4; i++) {
            int idx = tid + i * 128;
            int row = idx >> 3, c4 = (idx & 7) * 4;
            uint4 v = *(const uint4*)(Kh + (size_t)(b * Sn + k0 + row) * KP + h * 32 + c4);
            *(uint4*)&Ks[row][c4] = v;
        }
        // V tile: transpose into [dh][key-pair] via byte_perm
#pragma unroll
        for (int rr = 0; rr < 2; rr++) {
            int it = tid + rr * 128;
            int kp = it & 31, cg = it >> 5;            // cg 0..7
            const uint32_t* vb = Vh + (size_t)(b * Sn + k0 + 2 * kp) * KP + h * 32 + cg * 4;
            uint4 a  = *(const uint4*)vb;
            uint4 bq = *(const uint4*)(vb + KP);
            Vt[cg * 8 + 0][kp] = __byte_perm(a.x, bq.x, 0x5410);
            Vt[cg * 8 + 1][kp] = __byte_perm(a.x, bq.x, 0x7632);
            Vt[cg * 8 + 2][kp] = __byte_perm(a.y, bq.y, 0x5410);
            Vt[cg * 8 + 3][kp] = __byte_perm(a.y, bq.y, 0x7632);
            Vt[cg * 8 + 4][kp] = __byte_perm(a.z, bq.z, 0x5410);
            Vt[cg * 8 + 5][kp] = __byte_perm(a.z, bq.z, 0x7632);
            Vt[cg * 8 + 6][kp] = __byte_perm(a.w, bq.w, 0x5410);
            Vt[cg * 8 + 7][kp] = __byte_perm(a.w, bq.w, 0x7632);
        }
        __syncthreads();

        // ---- S = Q @ K^T (fp16, fp32 accum; Q pre-scaled) ----
        float cs[8][4];
#pragma unroll
        for (int j = 0; j < 8; j++) {
#pragma unroll
            for (int r = 0; r < 4; r++) cs[j][r] = 0.f;
#pragma unroll
            for (int ks = 0; ks < 4; ks++)
                mma_f16(cs[j], qf[ks],
                        Ks[j * 8 + grp][8 * ks + tg],
                        Ks[j * 8 + grp][8 * ks + tg + 4]);
        }

        // ---- causal mask (diagonal tile only) ----
        if (kt == qb) {
            const int r0 = q0 + m0 + grp;
            const int r1 = r0 + 8;
#pragma unroll
            for (int j = 0; j < 8; j++) {
                const int ca = k0 + j * 8 + 2 * tg;
                if (ca > r0)     cs[j][0] = -1e30f;
                if (ca + 1 > r0) cs[j][1] = -1e30f;
                if (ca > r1)     cs[j][2] = -1e30f;
                if (ca + 1 > r1) cs[j][3] = -1e30f;
            }
        }

        // ---- online softmax ----
        float mx0 = mr0, mx1 = mr1;
#pragma unroll
        for (int j = 0; j < 8; j++) {
            mx0 = fmaxf(mx0, fmaxf(cs[j][0], cs[j][1]));
            mx1 = fmaxf(mx1, fmaxf(cs[j][2], cs[j][3]));
        }
        mx0 = fmaxf(mx0, __shfl_xor_sync(0xffffffffu, mx0, 1));
        mx0 = fmaxf(mx0, __shfl_xor_sync(0xffffffffu, mx0, 2));
        mx1 = fmaxf(mx1, __shfl_xor_sync(0xffffffffu, mx1, 1));
        mx1 = fmaxf(mx1, __shfl_xor_sync(0xffffffffu, mx1, 2));

        float corr0 = __expf(mr0 - mx0);
        float corr1 = __expf(mr1 - mx1);
        mr0 = mx0; mr1 = mx1;

        float s0 = 0.f, s1 = 0.f;
#pragma unroll
        for (int j = 0; j < 8; j++) {
            cs[j][0] = __expf(cs[j][0] - mx0); s0 += cs[j][0];
            cs[j][1] = __expf(cs[j][1] - mx0); s0 += cs[j][1];
            cs[j][2] = __expf(cs[j][2] - mx1); s1 += cs[j][2];
            cs[j][3] = __expf(cs[j][3] - mx1); s1 += cs[j][3];
        }
        s0 += __shfl_xor_sync(0xffffffffu, s0, 1);
        s0 += __shfl_xor_sync(0xffffffffu, s0, 2);
        s1 += __shfl_xor_sync(0xffffffffu, s1, 1);
        s1 += __shfl_xor_sync(0xffffffffu, s1, 2);
        l0 = l0 * corr0 + s0;
        l1 = l1 * corr1 + s1;

#pragma unroll
        for (int j = 0; j < 8; j++) {
            co[j][0] *= corr0; co[j][1] *= corr0;
            co[j][2] *= corr1; co[j][3] *= corr1;
        }

        // ---- O += P @ V : P A-frags directly from S accumulator ----
#pragma unroll
        for (int kk = 0; kk < 4; kk++) {
            uint32_t ap[4];
            ap[0] = packh2(cs[2 * kk][0],     cs[2 * kk][1]);
            ap[1] = packh2(cs[2 * kk][2],     cs[2 * kk][3]);
            ap[2] = packh2(cs[2 * kk + 1][0], cs[2 * kk + 1][1]);
            ap[3] = packh2(cs[2 * kk + 1][2], cs[2 * kk + 1][3]);
#pragma unroll
            for (int j = 0; j < 8; j++)
                mma_f16(co[j], ap,
                        Vt[j * 8 + grp][8 * kk + tg],
                        Vt[j * 8 + grp][8 * kk + tg + 4]);
        }
        __syncthreads();
    }

    // ---- epilogue: fp16 pairs for the W_O GEMM ----
    const float i0 = 1.f / l0;
    const float i1 = 1.f / l1;
    const int r0 = q0 + m0 + grp;
    uint32_t* op0 = d_attnh + (size_t)(b * Sn + r0) * KP + (h * DH) / 2;
    uint32_t* op1 = d_attnh + (size_t)(b * Sn + r0 + 8) * KP + (h * DH) / 2;
#pragma unroll
    for (int j = 0; j < 8; j++) {
        const int p = j * 4 + tg;
        op0[p] = packh2(co[j][0] * i0, co[j][1] * i0);
        op1[p] = packh2(co[j][2] * i1, co[j][3] * i1);
    }
}

// ---------------------------------------------------------------------------
// Host launch
// ---------------------------------------------------------------------------
extern "C" void kernel_launch(void* const* d_in, const int* in_sizes, int n_in,
                              void* d_out, int out_size)
{
    const float* x    = (const float*)d_in[0];
    const float* qk_f = (const float*)d_in[1];
    const float* qk_r = (const float*)d_in[2];
    const float* v_f  = (const float*)d_in[3];
    const float* v_r  = (const float*)d_in[4];
    const float* Wgq  = (const float*)d_in[5];
    const float* Wgk  = (const float*)d_in[6];
    const float* Wgv  = (const float*)d_in[7];
    const float* W_O  = (const float*)d_in[8];
    float* out = (float*)d_out;

    uint32_t *xh, *bfeath, *brh, *attnh;
    float *cf;
    cudaGetSymbolAddress((void**)&xh,     d_xh);
    cudaGetSymbolAddress((void**)&bfeath, d_bfeath);
    cudaGetSymbolAddress((void**)&brh,    d_brh);
    cudaGetSymbolAddress((void**)&cf,     d_CF);
    cudaGetSymbolAddress((void**)&attnh,  d_attnh);

    static bool attrDone = false;
    if (!attrDone) {
        cudaFuncSetAttribute(gemm_h, cudaFuncAttributeMaxDynamicSharedMemorySize, SMEM_BYTES);
        cudaFuncSetAttribute(gemm_restore_h, cudaFuncAttributeMaxDynamicSharedMemorySize, SMEM_BYTES);
        attrDone = true;
    }

    dim3 t256(256);

    // 0) pack operands to fp16 pairs
    pack_xh<<<(BS * KP) / 256, t256>>>(x);
    pack_brh<<<dim3(4, KP, 3), t256>>>(qk_r, v_r, W_O);
    pack_bfeath<<<dim3(NF / 256, KP), t256>>>(Wgq, Wgk, Wgv, qk_f, v_f);

    // 1) Merged logits + features: [2048, 2816] = xh @ bfeath
    gemm_h<<<dim3(NF / 128, BS / 128, 1), t256, SMEM_BYTES>>>(
        xh, bfeath, cf, KP, NF, NF);

    // 2) Fused gates + mix + aeff (fp16 pairs)
    gma_kernel<<<BS, t256>>>();

    // 3) Restore: Q,K,V in one launch (z = 0..2), fp16-pair outputs
    gemm_restore_h<<<dim3(Dn / 128, BS / 128, 3), t256, SMEM_BYTES>>>();

    // 4) FP16 tensor-core causal attention
    flash_h_kernel<<<dim3(Sn / 64, Bn * NH), 128>>>();

    // 5) Output projection -> d_out
    gemm_h<<<dim3(Dn / 128, BS / 128, 1), t256, SMEM_BYTES>>>(
        attnh, brh + (size_t)2 * KP * Dn, out, KP, Dn, Dn);
}